// round 8
// baseline (speedup 1.0000x reference)
#include <cuda_runtime.h>
#include <cuda_bf16.h>
#include <cstdint>
#include <math.h>

// ---------------------------------------------------------------------------
// Model constants
// ---------------------------------------------------------------------------
#define N_LAYER 4
#define N_HEADS 16
#define C_DIM   1024
#define T_SEQ   1024
#define B_SZ    2
#define ROWS    (B_SZ * T_SEQ)      // 2048
#define F4_DIM  (4 * C_DIM)         // 4096
#define HEAD_D  64
#define VOCABP1 101
#define TRANS   16
#define K3C     (3 * C_DIM)         // 3072
#define K3F     (3 * F4_DIM)        // 12288
#define NQKV    (3 * C_DIM)         // 3072

// ---------------------------------------------------------------------------
// Static device scratch (no allocations allowed)
// ---------------------------------------------------------------------------
__device__ float g_x  [ROWS * C_DIM];
__device__ float g_h  [ROWS * C_DIM];
__device__ float g_qkv[ROWS * NQKV];

__device__ __nv_bfloat16 g_aexpC[(size_t)ROWS * K3C];
__device__ __nv_bfloat16 g_aexpF[(size_t)ROWS * K3F];

__device__ __nv_bfloat16 g_wqkv[(size_t)N_LAYER * NQKV * K3C];
__device__ __nv_bfloat16 g_wp  [(size_t)N_LAYER * C_DIM * K3C];
__device__ __nv_bfloat16 g_w1  [(size_t)N_LAYER * F4_DIM * K3C];
__device__ __nv_bfloat16 g_w2  [(size_t)N_LAYER * C_DIM * K3F];
__device__ float         g_bqkv[N_LAYER * NQKV];

// ---------------------------------------------------------------------------
// PTX helpers (sm_80-safe only; ptxas targets plain sm_103)
// ---------------------------------------------------------------------------
__device__ __forceinline__ uint32_t smem_u32(const void* p) {
    uint32_t a;
    asm("{ .reg .u64 t; cvta.to.shared.u64 t, %1; cvt.u32.u64 %0, t; }" : "=r"(a) : "l"(p));
    return a;
}
__device__ __forceinline__ void cp_async16(uint32_t s, const void* g) {
    asm volatile("cp.async.cg.shared.global [%0], [%1], 16;" :: "r"(s), "l"(g));
}
__device__ __forceinline__ void cp_commit() { asm volatile("cp.async.commit_group;"); }
template<int N> __device__ __forceinline__ void cp_wait() {
    asm volatile("cp.async.wait_group %0;" :: "n"(N));
}
__device__ __forceinline__ void ldsm_x4(uint32_t& r0, uint32_t& r1, uint32_t& r2, uint32_t& r3,
                                        uint32_t addr) {
    asm volatile("ldmatrix.sync.aligned.m8n8.x4.shared.b16 {%0,%1,%2,%3}, [%4];"
                 : "=r"(r0), "=r"(r1), "=r"(r2), "=r"(r3) : "r"(addr));
}
__device__ __forceinline__ void mma16816(float* c, const uint32_t* a, uint32_t b0, uint32_t b1) {
    asm volatile("mma.sync.aligned.m16n8k16.row.col.f32.bf16.bf16.f32 "
                 "{%0,%1,%2,%3}, {%4,%5,%6,%7}, {%8,%9}, {%0,%1,%2,%3};"
                 : "+f"(c[0]), "+f"(c[1]), "+f"(c[2]), "+f"(c[3])
                 : "r"(a[0]), "r"(a[1]), "r"(a[2]), "r"(a[3]), "r"(b0), "r"(b1));
}
__device__ __forceinline__ uint32_t swz(int r, int s8) {
    return (uint32_t)(r * 128 + ((s8 ^ (r & 7)) << 4));
}

// ---------------------------------------------------------------------------
// Embedding
// ---------------------------------------------------------------------------
__global__ void embed_kernel(const int* __restrict__ tokens,
                             const float* __restrict__ tok_emb,
                             const float* __restrict__ pos_emb,
                             float* __restrict__ X)
{
    int i = blockIdx.x * blockDim.x + threadIdx.x;
    int row = i >> 10;
    int c   = i & 1023;
    int t   = row & 1023;
    int tok = tokens[row];
    X[i] = tok_emb[(size_t)tok * C_DIM + c] + pos_emb[(size_t)t * C_DIM + c];
}

// ---------------------------------------------------------------------------
// bias concat for fused QKV
// ---------------------------------------------------------------------------
__global__ void bqkv_kernel(const float* __restrict__ bq, const float* __restrict__ bk,
                            const float* __restrict__ bv, float* __restrict__ out)
{
    int i = blockIdx.x * blockDim.x + threadIdx.x;
    int l = i / NQKV;
    int c = i - l * NQKV;
    float v;
    if (c < C_DIM)            v = bq[l * C_DIM + c];
    else if (c < 2 * C_DIM)   v = bk[l * C_DIM + c - C_DIM];
    else                      v = bv[l * C_DIM + c - 2 * C_DIM];
    out[i] = v;
}

// ---------------------------------------------------------------------------
// LayerNorm. EXP=0: fp32 Y. EXP=1: bf16 [hi|lo|hi] into Ye [row][3C]
// ---------------------------------------------------------------------------
template<int EXP>
__global__ void ln_kernel(const float* __restrict__ X,
                          const float* __restrict__ w,
                          const float* __restrict__ b,
                          float* __restrict__ Y, __nv_bfloat16* __restrict__ Ye)
{
    const int row = blockIdx.x;
    const float* x = X + (size_t)row * C_DIM;
    const int tid = threadIdx.x;

    float v[4];
    float s = 0.f;
#pragma unroll
    for (int i = 0; i < 4; ++i) { v[i] = x[tid + 256 * i]; s += v[i]; }

    __shared__ float red[8];
#pragma unroll
    for (int off = 16; off; off >>= 1) s += __shfl_xor_sync(~0u, s, off);
    if ((tid & 31) == 0) red[tid >> 5] = s;
    __syncthreads();
    float tot = 0.f;
#pragma unroll
    for (int j = 0; j < 8; ++j) tot += red[j];
    const float mu = tot * (1.0f / C_DIM);
    __syncthreads();

    float ss = 0.f;
#pragma unroll
    for (int i = 0; i < 4; ++i) { float d = v[i] - mu; ss += d * d; }
#pragma unroll
    for (int off = 16; off; off >>= 1) ss += __shfl_xor_sync(~0u, ss, off);
    if ((tid & 31) == 0) red[tid >> 5] = ss;
    __syncthreads();
    float tot2 = 0.f;
#pragma unroll
    for (int j = 0; j < 8; ++j) tot2 += red[j];
    const float rs = rsqrtf(tot2 * (1.0f / C_DIM) + 1e-5f);

#pragma unroll
    for (int i = 0; i < 4; ++i) {
        const int c = tid + 256 * i;
        const float o = (v[i] - mu) * rs * w[c] + b[c];
        if (EXP == 0) {
            Y[(size_t)row * C_DIM + c] = o;
        } else {
            __nv_bfloat16 hi = __float2bfloat16(o);
            __nv_bfloat16 lo = __float2bfloat16(o - __bfloat162float(hi));
            __nv_bfloat16* yr = Ye + (size_t)row * K3C;
            yr[c]             = hi;
            yr[C_DIM + c]     = lo;
            yr[2 * C_DIM + c] = hi;
        }
    }
}

// ---------------------------------------------------------------------------
// Split+transpose weight W [K,N] -> bf16 B' [N, 3K] = [hi | hi | lo]
// ---------------------------------------------------------------------------
__global__ void expand_wT(const float* __restrict__ W, __nv_bfloat16* __restrict__ out,
                          int K, int N)
{
    __shared__ float t[32][33];
    const int k0 = blockIdx.x * 32, n0 = blockIdx.y * 32;
    const int tx = threadIdx.x, ty = threadIdx.y;
#pragma unroll
    for (int i = 0; i < 4; ++i)
        t[ty + 8 * i][tx] = W[(size_t)(k0 + ty + 8 * i) * N + n0 + tx];
    __syncthreads();
#pragma unroll
    for (int i = 0; i < 4; ++i) {
        int n = n0 + ty + 8 * i;
        int k = k0 + tx;
        float x = t[tx][ty + 8 * i];
        __nv_bfloat16 hi = __float2bfloat16(x);
        __nv_bfloat16 lo = __float2bfloat16(x - __bfloat162float(hi));
        size_t base = (size_t)n * 3 * K;
        out[base + k]         = hi;
        out[base + K + k]     = hi;
        out[base + 2 * K + k] = lo;
    }
}

// ---------------------------------------------------------------------------
// HMMA bf16 GEMM: 128x128 tile, BK=64, 3-stage cp.async, frag double-buffer.
// EPI: 1 = bias -> Cf; 2 = bias+residual -> Cf; 3 = bias+gelu -> Ce [hi|lo|hi]
// ---------------------------------------------------------------------------
#define G_STAGES 3
#define G_TILEB  (128 * 128)
#define G_STAGEB (2 * G_TILEB)
#define G_SMEM   (G_STAGES * G_STAGEB)

template<int EPI>
__global__ __launch_bounds__(256)
void mma_gemm(const __nv_bfloat16* __restrict__ A, const __nv_bfloat16* __restrict__ B,
              const float* __restrict__ bias, const float* __restrict__ R,
              float* __restrict__ Cf, __nv_bfloat16* __restrict__ Ce,
              int N, int K3)
{
    extern __shared__ char smem[];
    const uint32_t sbase = smem_u32(smem);
    const int tid  = threadIdx.x;
    const int wid  = tid >> 5, lane = tid & 31;
    const int warp_m = wid >> 2, warp_n = wid & 3;
    const int bx = blockIdx.x, by = blockIdx.y;

    const char* Abase = (const char*)(A + (size_t)(by * 128) * K3);
    const char* Bbase = (const char*)(B + (size_t)(bx * 128) * K3);
    const size_t ldg = (size_t)K3 * 2;
    const int nchunks = K3 >> 6;

    const int r_cp[4] = { tid >> 3, (tid + 256) >> 3, (tid + 512) >> 3, (tid + 768) >> 3 };
    const int s8_cp   = tid & 7;

#pragma unroll
    for (int st = 0; st < G_STAGES - 1; ++st) {
        const uint32_t sb = sbase + st * G_STAGEB;
#pragma unroll
        for (int p = 0; p < 4; ++p) {
            const int r = r_cp[p];
            cp_async16(sb + swz(r, s8_cp),           Abase + (size_t)r * ldg + st * 128 + s8_cp * 16);
            cp_async16(sb + G_TILEB + swz(r, s8_cp), Bbase + (size_t)r * ldg + st * 128 + s8_cp * 16);
        }
        cp_commit();
    }

    float acc[4][4][4];
#pragma unroll
    for (int i = 0; i < 4; ++i)
#pragma unroll
        for (int j = 0; j < 4; ++j)
#pragma unroll
            for (int r = 0; r < 4; ++r) acc[i][j][r] = 0.f;

    const int a_r0 = warp_m * 64 + (lane & 15);
    const int a_s0 = lane >> 4;
    const int b_r0 = warp_n * 32 + (lane & 7) + ((lane >> 4) << 3);
    const int b_s0 = (lane >> 3) & 1;

    for (int c = 0; c < nchunks; ++c) {
        cp_wait<G_STAGES - 2>();
        __syncthreads();

        const int nc = c + G_STAGES - 1;
        if (nc < nchunks) {
            const uint32_t nb = sbase + (nc % G_STAGES) * G_STAGEB;
#pragma unroll
            for (int p = 0; p < 4; ++p) {
                const int r = r_cp[p];
                cp_async16(nb + swz(r, s8_cp),           Abase + (size_t)r * ldg + nc * 128 + s8_cp * 16);
                cp_async16(nb + G_TILEB + swz(r, s8_cp), Bbase + (size_t)r * ldg + nc * 128 + s8_cp * 16);
            }
        }
        cp_commit();

        const uint32_t sb = sbase + (c % G_STAGES) * G_STAGEB;

        // fragment double-buffer across the 4 K-substeps
        uint32_t af[2][4][4], bfr[2][2][4];
#pragma unroll
        for (int ma = 0; ma < 4; ++ma)
            ldsm_x4(af[0][ma][0], af[0][ma][1], af[0][ma][2], af[0][ma][3],
                    sb + swz(a_r0 + ma * 16, a_s0));
#pragma unroll
        for (int j = 0; j < 2; ++j)
            ldsm_x4(bfr[0][j][0], bfr[0][j][1], bfr[0][j][2], bfr[0][j][3],
                    sb + G_TILEB + swz(b_r0 + j * 16, b_s0));

#pragma unroll
        for (int ks = 0; ks < 4; ++ks) {
            const int cur = ks & 1, nxt = cur ^ 1;
            if (ks < 3) {
#pragma unroll
                for (int ma = 0; ma < 4; ++ma)
                    ldsm_x4(af[nxt][ma][0], af[nxt][ma][1], af[nxt][ma][2], af[nxt][ma][3],
                            sb + swz(a_r0 + ma * 16, (ks + 1) * 2 + a_s0));
#pragma unroll
                for (int j = 0; j < 2; ++j)
                    ldsm_x4(bfr[nxt][j][0], bfr[nxt][j][1], bfr[nxt][j][2], bfr[nxt][j][3],
                            sb + G_TILEB + swz(b_r0 + j * 16, (ks + 1) * 2 + b_s0));
            }
#pragma unroll
            for (int ma = 0; ma < 4; ++ma)
#pragma unroll
                for (int na = 0; na < 4; ++na)
                    mma16816(acc[ma][na], af[cur][ma], bfr[cur][na >> 1][(na & 1) * 2],
                             bfr[cur][na >> 1][(na & 1) * 2 + 1]);
        }
    }

    // epilogue
#pragma unroll
    for (int ma = 0; ma < 4; ++ma) {
        const int row0 = by * 128 + warp_m * 64 + ma * 16 + (lane >> 2);
        const int row1 = row0 + 8;
#pragma unroll
        for (int na = 0; na < 4; ++na) {
            const int col = bx * 128 + warp_n * 32 + na * 8 + (lane & 3) * 2;
            float v0 = acc[ma][na][0] + bias[col];
            float v1 = acc[ma][na][1] + bias[col + 1];
            float v2 = acc[ma][na][2] + bias[col];
            float v3 = acc[ma][na][3] + bias[col + 1];
            if (EPI == 2) {
                v0 += R[(size_t)row0 * N + col];     v1 += R[(size_t)row0 * N + col + 1];
                v2 += R[(size_t)row1 * N + col];     v3 += R[(size_t)row1 * N + col + 1];
            }
            if (EPI == 3) {
                v0 = 0.5f * v0 * (1.0f + erff(v0 * 0.70710678118654752f));
                v1 = 0.5f * v1 * (1.0f + erff(v1 * 0.70710678118654752f));
                v2 = 0.5f * v2 * (1.0f + erff(v2 * 0.70710678118654752f));
                v3 = 0.5f * v3 * (1.0f + erff(v3 * 0.70710678118654752f));
                __nv_bfloat162 h0, l0, h1, l1;
                h0.x = __float2bfloat16(v0); h0.y = __float2bfloat16(v1);
                l0.x = __float2bfloat16(v0 - __bfloat162float(h0.x));
                l0.y = __float2bfloat16(v1 - __bfloat162float(h0.y));
                h1.x = __float2bfloat16(v2); h1.y = __float2bfloat16(v3);
                l1.x = __float2bfloat16(v2 - __bfloat162float(h1.x));
                l1.y = __float2bfloat16(v3 - __bfloat162float(h1.y));
                __nv_bfloat16* c0 = Ce + (size_t)row0 * 3 * N;
                __nv_bfloat16* c1 = Ce + (size_t)row1 * 3 * N;
                *reinterpret_cast<__nv_bfloat162*>(c0 + col)         = h0;
                *reinterpret_cast<__nv_bfloat162*>(c0 + N + col)     = l0;
                *reinterpret_cast<__nv_bfloat162*>(c0 + 2 * N + col) = h0;
                *reinterpret_cast<__nv_bfloat162*>(c1 + col)         = h1;
                *reinterpret_cast<__nv_bfloat162*>(c1 + N + col)     = l1;
                *reinterpret_cast<__nv_bfloat162*>(c1 + 2 * N + col) = h1;
            } else {
                *reinterpret_cast<float2*>(Cf + (size_t)row0 * N + col) = make_float2(v0, v1);
                *reinterpret_cast<float2*>(Cf + (size_t)row1 * N + col) = make_float2(v2, v3);
            }
        }
    }
}

// ---------------------------------------------------------------------------
// Attention v2: lane-per-key online softmax.
// block = 8 warps, warp <-> one query row; lanes own distinct keys.
// K/V tiles in SMEM (65-float stride, conflict-free); merge via SMEM column
// reduce reusing the tile buffer (4 regions x 32x65 = exactly tile size).
// Output: expanded bf16 [hi|lo|hi] into Ye [row][3C].
// ---------------------------------------------------------------------------
#define ATT_PAD 65
__global__ __launch_bounds__(256)
void attn_kernel(const float* __restrict__ QKV, __nv_bfloat16* __restrict__ Ye)
{
    __shared__ float sm[2 * 64 * ATT_PAD];   // K tile | V tile; reused for merge
    float* Ksm = sm;
    float* Vsm = sm + 64 * ATT_PAD;

    const int bh = blockIdx.x, b = bh >> 4, h = bh & 15;
    const int qbase = blockIdx.y * 8;
    const int warp = threadIdx.x >> 5, lane = threadIdx.x & 31;
    const int tq = qbase + warp;
    const int row = b * T_SEQ + tq;

    const float* qp = QKV + (size_t)row * NQKV + h * HEAD_D;
    float qreg[64];
#pragma unroll
    for (int d = 0; d < 64; ++d) qreg[d] = qp[d];

    float m = -INFINITY, l = 0.f;
    float acc[64];
#pragma unroll
    for (int d = 0; d < 64; ++d) acc[d] = 0.f;

    const int smax = qbase + 7;
    for (int s0 = 0; s0 <= smax; s0 += 64) {
        const int tile = min(64, smax + 1 - s0);
        __syncthreads();
        for (int idx = threadIdx.x; idx < 64 * 64; idx += 256) {
            const int r = idx >> 6, cc = idx & 63;
            float kv = 0.f, vv = 0.f;
            if (r < tile) {
                const size_t g = (size_t)(b * T_SEQ + s0 + r) * NQKV + h * HEAD_D + cc;
                kv = QKV[g + C_DIM];
                vv = QKV[g + 2 * C_DIM];
            }
            Ksm[r * ATT_PAD + cc] = kv;
            Vsm[r * ATT_PAD + cc] = vv;
        }
        __syncthreads();

#pragma unroll
        for (int half = 0; half < 2; ++half) {
            if (s0 + half * 32 > tq) break;           // warp-uniform
            const int key = s0 + half * 32 + lane;
            const bool valid = (key <= tq) && ((key & 15) != 15);
            const float* kr = Ksm + (half * 32 + lane) * ATT_PAD;
            float p0 = 0.f, p1 = 0.f;
#pragma unroll
            for (int d = 0; d < 64; d += 2) {
                p0 += qreg[d]     * kr[d];
                p1 += qreg[d + 1] * kr[d + 1];
            }
            const float p  = (p0 + p1) * 0.125f;
            const float pv = valid ? p : -INFINITY;
            const float mnew = fmaxf(m, pv);
            const float corr = (mnew == m) ? 1.f : __expf(m - mnew);
            const float wgt  = valid ? __expf(p - mnew) : 0.f;
            l = l * corr + wgt;
            const float* vr = Vsm + (half * 32 + lane) * ATT_PAD;
#pragma unroll
            for (int d = 0; d < 64; ++d) acc[d] = acc[d] * corr + wgt * vr[d];
            m = mnew;
        }
    }

    // cross-lane merge
    float M = m;
#pragma unroll
    for (int off = 16; off; off >>= 1) M = fmaxf(M, __shfl_xor_sync(~0u, M, off));
    const float sc = __expf(m - M);                // m=-inf -> 0
    float lw = l * sc;
#pragma unroll
    for (int off = 16; off; off >>= 1) lw += __shfl_xor_sync(~0u, lw, off);
    const float inv = 1.0f / lw;

    __syncthreads();                                // tiles no longer needed
    float* scr = sm + (warp & 3) * (32 * ATT_PAD);
    float o0 = 0.f, o1 = 0.f;
#pragma unroll
    for (int ph = 0; ph < 2; ++ph) {
        if ((warp >> 2) == ph) {
#pragma unroll
            for (int d = 0; d < 64; ++d) scr[lane * ATT_PAD + d] = acc[d] * sc;
            __syncwarp();
            float t0 = 0.f, t1 = 0.f;
#pragma unroll
            for (int k2 = 0; k2 < 32; ++k2) {
                t0 += scr[k2 * ATT_PAD + lane];
                t1 += scr[k2 * ATT_PAD + 32 + lane];
            }
            o0 = t0 * inv; o1 = t1 * inv;
        }
        __syncthreads();
    }

    const int c0 = h * HEAD_D + lane;
    __nv_bfloat16 h0 = __float2bfloat16(o0);
    __nv_bfloat16 lo0 = __float2bfloat16(o0 - __bfloat162float(h0));
    __nv_bfloat16 h1 = __float2bfloat16(o1);
    __nv_bfloat16 lo1 = __float2bfloat16(o1 - __bfloat162float(h1));
    __nv_bfloat16* yr = Ye + (size_t)row * K3C;
    yr[c0]                 = h0;
    yr[C_DIM + c0]         = lo0;
    yr[2 * C_DIM + c0]     = h0;
    yr[c0 + 32]            = h1;
    yr[C_DIM + c0 + 32]    = lo1;
    yr[2 * C_DIM + c0 + 32] = h1;
}

// ---------------------------------------------------------------------------
// EinLinear head
// ---------------------------------------------------------------------------
__global__ __launch_bounds__(256)
void head_kernel(const float* __restrict__ X, const float* __restrict__ Wh,
                 float* __restrict__ out)
{
    const int e     = blockIdx.x & 15;
    const int chunk = blockIdx.x >> 4;
    const int tid = threadIdx.x;
    const int warp = tid >> 5, lane = tid & 31;

    __shared__ float xs[8][C_DIM];
    int rows[8];
#pragma unroll
    for (int j = 0; j < 8; ++j) rows[j] = (chunk * 8 + j) * TRANS + e;

#pragma unroll
    for (int j = 0; j < 8; ++j)
        for (int idx = tid; idx < C_DIM; idx += 256)
            xs[j][idx] = X[(size_t)rows[j] * C_DIM + idx];
    __syncthreads();

    for (int o = warp; o < VOCABP1; o += 8) {
        const float* w = Wh + ((size_t)e * VOCABP1 + o) * C_DIM;
        float a[8];
#pragma unroll
        for (int j = 0; j < 8; ++j) a[j] = 0.f;
        for (int k = lane; k < C_DIM; k += 32) {
            const float wv = w[k];
#pragma unroll
            for (int j = 0; j < 8; ++j) a[j] += wv * xs[j][k];
        }
#pragma unroll
        for (int j = 0; j < 8; ++j)
#pragma unroll
            for (int off = 16; off; off >>= 1)
                a[j] += __shfl_xor_sync(~0u, a[j], off);
        if (lane == 0) {
#pragma unroll
            for (int j = 0; j < 8; ++j)
                out[(size_t)rows[j] * VOCABP1 + o] = a[j];
        }
    }
}

// ---------------------------------------------------------------------------
// Launch
// ---------------------------------------------------------------------------
extern "C" void kernel_launch(void* const* d_in, const int* in_sizes, int n_in,
                              void* d_out, int out_size)
{
    const int*   tokens  = (const int*)  d_in[0];
    const float* tok_emb = (const float*)d_in[1];
    const float* pos_emb = (const float*)d_in[2];
    const float* Wq = (const float*)d_in[3];  const float* bq = (const float*)d_in[4];
    const float* Wk = (const float*)d_in[5];  const float* bk = (const float*)d_in[6];
    const float* Wv = (const float*)d_in[7];  const float* bv = (const float*)d_in[8];
    const float* Wp = (const float*)d_in[9];  const float* bp = (const float*)d_in[10];
    const float* ln1w = (const float*)d_in[11]; const float* ln1b = (const float*)d_in[12];
    const float* ln2w = (const float*)d_in[13]; const float* ln2b = (const float*)d_in[14];
    const float* W1 = (const float*)d_in[15]; const float* b1 = (const float*)d_in[16];
    const float* W2 = (const float*)d_in[17]; const float* b2 = (const float*)d_in[18];
    const float* lnfw = (const float*)d_in[19]; const float* lnfb = (const float*)d_in[20];
    const float* head_w = (const float*)d_in[21];

    float *x, *h, *qkv, *bqkv;
    __nv_bfloat16 *aC, *aF, *wqkvx, *wpx, *w1x, *w2x;
    cudaGetSymbolAddress((void**)&x,    g_x);
    cudaGetSymbolAddress((void**)&h,    g_h);
    cudaGetSymbolAddress((void**)&qkv,  g_qkv);
    cudaGetSymbolAddress((void**)&bqkv, g_bqkv);
    cudaGetSymbolAddress((void**)&aC,   g_aexpC);
    cudaGetSymbolAddress((void**)&aF,   g_aexpF);
    cudaGetSymbolAddress((void**)&wqkvx, g_wqkv);
    cudaGetSymbolAddress((void**)&wpx,  g_wp);
    cudaGetSymbolAddress((void**)&w1x,  g_w1);
    cudaGetSymbolAddress((void**)&w2x,  g_w2);

    cudaFuncSetAttribute(mma_gemm<1>, cudaFuncAttributeMaxDynamicSharedMemorySize, G_SMEM);
    cudaFuncSetAttribute(mma_gemm<2>, cudaFuncAttributeMaxDynamicSharedMemorySize, G_SMEM);
    cudaFuncSetAttribute(mma_gemm<3>, cudaFuncAttributeMaxDynamicSharedMemorySize, G_SMEM);

    const dim3 wb(32, 8);
    for (int i = 0; i < N_LAYER; ++i) {
        const size_t wc = (size_t)i * C_DIM * C_DIM;
        __nv_bfloat16* wl = wqkvx + (size_t)i * NQKV * K3C;
        expand_wT<<<dim3(32, 32), wb>>>(Wq + wc, wl,                           C_DIM, C_DIM);
        expand_wT<<<dim3(32, 32), wb>>>(Wk + wc, wl + (size_t)C_DIM * K3C,     C_DIM, C_DIM);
        expand_wT<<<dim3(32, 32), wb>>>(Wv + wc, wl + (size_t)2 * C_DIM * K3C, C_DIM, C_DIM);
        expand_wT<<<dim3(32, 32), wb>>>(Wp + wc, wpx + (size_t)i * C_DIM * K3C, C_DIM, C_DIM);
        expand_wT<<<dim3(32, 128), wb>>>(W1 + (size_t)i * C_DIM * F4_DIM,
                                         w1x + (size_t)i * F4_DIM * K3C, C_DIM, F4_DIM);
        expand_wT<<<dim3(128, 32), wb>>>(W2 + (size_t)i * F4_DIM * C_DIM,
                                         w2x + (size_t)i * C_DIM * K3F, F4_DIM, C_DIM);
    }
    bqkv_kernel<<<N_LAYER * NQKV / 256, 256>>>(bq, bk, bv, bqkv);

    embed_kernel<<<ROWS * C_DIM / 256, 256>>>(tokens, tok_emb, pos_emb, x);

    const dim3 gQKV(NQKV   / 128, ROWS / 128);
    const dim3 gC  (C_DIM  / 128, ROWS / 128);
    const dim3 gF4 (F4_DIM / 128, ROWS / 128);

    for (int i = 0; i < N_LAYER; ++i) {
        const size_t bc = (size_t)i * C_DIM;

        ln_kernel<1><<<ROWS, 256>>>(x, ln1w + bc, ln1b + bc, nullptr, aC);
        mma_gemm<1><<<gQKV, 256, G_SMEM>>>(aC, wqkvx + (size_t)i * NQKV * K3C,
                                           bqkv + (size_t)i * NQKV, nullptr,
                                           qkv, nullptr, NQKV, K3C);

        attn_kernel<<<dim3(B_SZ * N_HEADS, T_SEQ / 8), 256>>>(qkv, aC);

        mma_gemm<2><<<gC, 256, G_SMEM>>>(aC, wpx + (size_t)i * C_DIM * K3C,
                                         bp + bc, x, x, nullptr, C_DIM, K3C);

        ln_kernel<1><<<ROWS, 256>>>(x, ln2w + bc, ln2b + bc, nullptr, aC);
        mma_gemm<3><<<gF4, 256, G_SMEM>>>(aC, w1x + (size_t)i * F4_DIM * K3C,
                                          b1 + (size_t)i * F4_DIM, nullptr,
                                          nullptr, aF, F4_DIM, K3C);

        mma_gemm<2><<<gC, 256, G_SMEM>>>(aF, w2x + (size_t)i * C_DIM * K3F,
                                         b2 + bc, x, x, nullptr, C_DIM, K3F);
    }

    ln_kernel<0><<<ROWS, 256>>>(x, lnfw, lnfb, h, nullptr);
    head_kernel<<<256, 256>>>(h, head_w, (float*)d_out);
}

// round 9
// speedup vs baseline: 1.3554x; 1.3554x over previous
#include <cuda_runtime.h>
#include <cuda_bf16.h>
#include <cstdint>
#include <math.h>

// ---------------------------------------------------------------------------
// Model constants
// ---------------------------------------------------------------------------
#define N_LAYER 4
#define N_HEADS 16
#define C_DIM   1024
#define T_SEQ   1024
#define B_SZ    2
#define ROWS    (B_SZ * T_SEQ)      // 2048
#define F4_DIM  (4 * C_DIM)         // 4096
#define HEAD_D  64
#define VOCABP1 101
#define TRANS   16
#define K3C     (3 * C_DIM)         // 3072
#define K3F     (3 * F4_DIM)        // 12288
#define NQKV    (3 * C_DIM)         // 3072

// ---------------------------------------------------------------------------
// Static device scratch (no allocations allowed)
// ---------------------------------------------------------------------------
__device__ float g_x  [ROWS * C_DIM];
__device__ float g_h  [ROWS * C_DIM];
__device__ float g_qkv[ROWS * NQKV];

__device__ __nv_bfloat16 g_aexpC[(size_t)ROWS * K3C];
__device__ __nv_bfloat16 g_aexpF[(size_t)ROWS * K3F];

__device__ __nv_bfloat16 g_wqkv[(size_t)N_LAYER * NQKV * K3C];
__device__ __nv_bfloat16 g_wp  [(size_t)N_LAYER * C_DIM * K3C];
__device__ __nv_bfloat16 g_w1  [(size_t)N_LAYER * F4_DIM * K3C];
__device__ __nv_bfloat16 g_w2  [(size_t)N_LAYER * C_DIM * K3F];
__device__ float         g_bqkv[N_LAYER * NQKV];

// ---------------------------------------------------------------------------
// PTX helpers (sm_80-safe only; ptxas targets plain sm_103)
// ---------------------------------------------------------------------------
__device__ __forceinline__ uint32_t smem_u32(const void* p) {
    uint32_t a;
    asm("{ .reg .u64 t; cvta.to.shared.u64 t, %1; cvt.u32.u64 %0, t; }" : "=r"(a) : "l"(p));
    return a;
}
__device__ __forceinline__ void cp_async16(uint32_t s, const void* g) {
    asm volatile("cp.async.cg.shared.global [%0], [%1], 16;" :: "r"(s), "l"(g));
}
__device__ __forceinline__ void cp_commit() { asm volatile("cp.async.commit_group;"); }
template<int N> __device__ __forceinline__ void cp_wait() {
    asm volatile("cp.async.wait_group %0;" :: "n"(N));
}
__device__ __forceinline__ void ldsm_x4(uint32_t& r0, uint32_t& r1, uint32_t& r2, uint32_t& r3,
                                        uint32_t addr) {
    asm volatile("ldmatrix.sync.aligned.m8n8.x4.shared.b16 {%0,%1,%2,%3}, [%4];"
                 : "=r"(r0), "=r"(r1), "=r"(r2), "=r"(r3) : "r"(addr));
}
__device__ __forceinline__ void mma16816(float* c, const uint32_t* a, uint32_t b0, uint32_t b1) {
    asm volatile("mma.sync.aligned.m16n8k16.row.col.f32.bf16.bf16.f32 "
                 "{%0,%1,%2,%3}, {%4,%5,%6,%7}, {%8,%9}, {%0,%1,%2,%3};"
                 : "+f"(c[0]), "+f"(c[1]), "+f"(c[2]), "+f"(c[3])
                 : "r"(a[0]), "r"(a[1]), "r"(a[2]), "r"(a[3]), "r"(b0), "r"(b1));
}
__device__ __forceinline__ uint32_t swz(int r, int s8) {
    return (uint32_t)(r * 128 + ((s8 ^ (r & 7)) << 4));
}

// ---------------------------------------------------------------------------
// Embedding
// ---------------------------------------------------------------------------
__global__ void embed_kernel(const int* __restrict__ tokens,
                             const float* __restrict__ tok_emb,
                             const float* __restrict__ pos_emb,
                             float* __restrict__ X)
{
    int i = blockIdx.x * blockDim.x + threadIdx.x;
    int row = i >> 10;
    int c   = i & 1023;
    int t   = row & 1023;
    int tok = tokens[row];
    X[i] = tok_emb[(size_t)tok * C_DIM + c] + pos_emb[(size_t)t * C_DIM + c];
}

// ---------------------------------------------------------------------------
// bias concat for fused QKV
// ---------------------------------------------------------------------------
__global__ void bqkv_kernel(const float* __restrict__ bq, const float* __restrict__ bk,
                            const float* __restrict__ bv, float* __restrict__ out)
{
    int i = blockIdx.x * blockDim.x + threadIdx.x;
    int l = i / NQKV;
    int c = i - l * NQKV;
    float v;
    if (c < C_DIM)            v = bq[l * C_DIM + c];
    else if (c < 2 * C_DIM)   v = bk[l * C_DIM + c - C_DIM];
    else                      v = bv[l * C_DIM + c - 2 * C_DIM];
    out[i] = v;
}

// ---------------------------------------------------------------------------
// LayerNorm. EXP=0: fp32 Y. EXP=1: bf16 [hi|lo|hi] into Ye [row][3C]
// ---------------------------------------------------------------------------
template<int EXP>
__global__ void ln_kernel(const float* __restrict__ X,
                          const float* __restrict__ w,
                          const float* __restrict__ b,
                          float* __restrict__ Y, __nv_bfloat16* __restrict__ Ye)
{
    const int row = blockIdx.x;
    const float* x = X + (size_t)row * C_DIM;
    const int tid = threadIdx.x;

    float v[4];
    float s = 0.f;
#pragma unroll
    for (int i = 0; i < 4; ++i) { v[i] = x[tid + 256 * i]; s += v[i]; }

    __shared__ float red[8];
#pragma unroll
    for (int off = 16; off; off >>= 1) s += __shfl_xor_sync(~0u, s, off);
    if ((tid & 31) == 0) red[tid >> 5] = s;
    __syncthreads();
    float tot = 0.f;
#pragma unroll
    for (int j = 0; j < 8; ++j) tot += red[j];
    const float mu = tot * (1.0f / C_DIM);
    __syncthreads();

    float ss = 0.f;
#pragma unroll
    for (int i = 0; i < 4; ++i) { float d = v[i] - mu; ss += d * d; }
#pragma unroll
    for (int off = 16; off; off >>= 1) ss += __shfl_xor_sync(~0u, ss, off);
    if ((tid & 31) == 0) red[tid >> 5] = ss;
    __syncthreads();
    float tot2 = 0.f;
#pragma unroll
    for (int j = 0; j < 8; ++j) tot2 += red[j];
    const float rs = rsqrtf(tot2 * (1.0f / C_DIM) + 1e-5f);

#pragma unroll
    for (int i = 0; i < 4; ++i) {
        const int c = tid + 256 * i;
        const float o = (v[i] - mu) * rs * w[c] + b[c];
        if (EXP == 0) {
            Y[(size_t)row * C_DIM + c] = o;
        } else {
            __nv_bfloat16 hi = __float2bfloat16(o);
            __nv_bfloat16 lo = __float2bfloat16(o - __bfloat162float(hi));
            __nv_bfloat16* yr = Ye + (size_t)row * K3C;
            yr[c]             = hi;
            yr[C_DIM + c]     = lo;
            yr[2 * C_DIM + c] = hi;
        }
    }
}

// ---------------------------------------------------------------------------
// Split+transpose weight W [K,N] -> bf16 B' [N, 3K] = [hi | hi | lo]
// ---------------------------------------------------------------------------
__global__ void expand_wT(const float* __restrict__ W, __nv_bfloat16* __restrict__ out,
                          int K, int N)
{
    __shared__ float t[32][33];
    const int k0 = blockIdx.x * 32, n0 = blockIdx.y * 32;
    const int tx = threadIdx.x, ty = threadIdx.y;
#pragma unroll
    for (int i = 0; i < 4; ++i)
        t[ty + 8 * i][tx] = W[(size_t)(k0 + ty + 8 * i) * N + n0 + tx];
    __syncthreads();
#pragma unroll
    for (int i = 0; i < 4; ++i) {
        int n = n0 + ty + 8 * i;
        int k = k0 + tx;
        float x = t[tx][ty + 8 * i];
        __nv_bfloat16 hi = __float2bfloat16(x);
        __nv_bfloat16 lo = __float2bfloat16(x - __bfloat162float(hi));
        size_t base = (size_t)n * 3 * K;
        out[base + k]         = hi;
        out[base + K + k]     = hi;
        out[base + 2 * K + k] = lo;
    }
}

// ---------------------------------------------------------------------------
// HMMA bf16 GEMM (round-7 mainloop + 2-CTA/SM occupancy):
// 128x128 tile, BK=64, 8 warps (2Mx4N), 3-stage cp.async, single sync/chunk.
// __launch_bounds__(256, 2): 2 CTAs/SM (192KB smem, regs capped at 128).
// EPI: 1 = bias -> Cf; 2 = bias+residual -> Cf; 3 = bias+gelu -> Ce [hi|lo|hi]
// ---------------------------------------------------------------------------
#define G_STAGES 3
#define G_TILEB  (128 * 128)
#define G_STAGEB (2 * G_TILEB)
#define G_SMEM   (G_STAGES * G_STAGEB)   // 98304

template<int EPI>
__global__ __launch_bounds__(256, 2)
void mma_gemm(const __nv_bfloat16* __restrict__ A, const __nv_bfloat16* __restrict__ B,
              const float* __restrict__ bias, const float* __restrict__ R,
              float* __restrict__ Cf, __nv_bfloat16* __restrict__ Ce,
              int N, int K3)
{
    extern __shared__ char smem[];
    const uint32_t sbase = smem_u32(smem);
    const int tid  = threadIdx.x;
    const int wid  = tid >> 5, lane = tid & 31;
    const int warp_m = wid >> 2, warp_n = wid & 3;
    const int bx = blockIdx.x, by = blockIdx.y;

    const char* Abase = (const char*)(A + (size_t)(by * 128) * K3);
    const char* Bbase = (const char*)(B + (size_t)(bx * 128) * K3);
    const size_t ldg = (size_t)K3 * 2;
    const int nchunks = K3 >> 6;

    const int r_cp[4] = { tid >> 3, (tid + 256) >> 3, (tid + 512) >> 3, (tid + 768) >> 3 };
    const int s8_cp   = tid & 7;

#pragma unroll
    for (int st = 0; st < G_STAGES - 1; ++st) {
        const uint32_t sb = sbase + st * G_STAGEB;
#pragma unroll
        for (int p = 0; p < 4; ++p) {
            const int r = r_cp[p];
            cp_async16(sb + swz(r, s8_cp),           Abase + (size_t)r * ldg + st * 128 + s8_cp * 16);
            cp_async16(sb + G_TILEB + swz(r, s8_cp), Bbase + (size_t)r * ldg + st * 128 + s8_cp * 16);
        }
        cp_commit();
    }

    float acc[4][4][4];
#pragma unroll
    for (int i = 0; i < 4; ++i)
#pragma unroll
        for (int j = 0; j < 4; ++j)
#pragma unroll
            for (int r = 0; r < 4; ++r) acc[i][j][r] = 0.f;

    const int a_r0 = warp_m * 64 + (lane & 15);
    const int a_s0 = lane >> 4;
    const int b_r0 = warp_n * 32 + (lane & 7) + ((lane >> 4) << 3);
    const int b_s0 = (lane >> 3) & 1;

    for (int c = 0; c < nchunks; ++c) {
        cp_wait<G_STAGES - 2>();
        __syncthreads();

        const int nc = c + G_STAGES - 1;
        if (nc < nchunks) {
            const uint32_t nb = sbase + (nc % G_STAGES) * G_STAGEB;
#pragma unroll
            for (int p = 0; p < 4; ++p) {
                const int r = r_cp[p];
                cp_async16(nb + swz(r, s8_cp),           Abase + (size_t)r * ldg + nc * 128 + s8_cp * 16);
                cp_async16(nb + G_TILEB + swz(r, s8_cp), Bbase + (size_t)r * ldg + nc * 128 + s8_cp * 16);
            }
        }
        cp_commit();

        const uint32_t sb = sbase + (c % G_STAGES) * G_STAGEB;
#pragma unroll
        for (int ks = 0; ks < 4; ++ks) {
            uint32_t af[4][4], bfr[2][4];
#pragma unroll
            for (int ma = 0; ma < 4; ++ma) {
                const int r = a_r0 + ma * 16;
                ldsm_x4(af[ma][0], af[ma][1], af[ma][2], af[ma][3],
                        sb + swz(r, ks * 2 + a_s0));
            }
#pragma unroll
            for (int j = 0; j < 2; ++j) {
                const int r = b_r0 + j * 16;
                ldsm_x4(bfr[j][0], bfr[j][1], bfr[j][2], bfr[j][3],
                        sb + G_TILEB + swz(r, ks * 2 + b_s0));
            }
#pragma unroll
            for (int ma = 0; ma < 4; ++ma)
#pragma unroll
                for (int na = 0; na < 4; ++na)
                    mma16816(acc[ma][na], af[ma], bfr[na >> 1][(na & 1) * 2],
                             bfr[na >> 1][(na & 1) * 2 + 1]);
        }
    }

    // epilogue
#pragma unroll
    for (int ma = 0; ma < 4; ++ma) {
        const int row0 = by * 128 + warp_m * 64 + ma * 16 + (lane >> 2);
        const int row1 = row0 + 8;
#pragma unroll
        for (int na = 0; na < 4; ++na) {
            const int col = bx * 128 + warp_n * 32 + na * 8 + (lane & 3) * 2;
            float v0 = acc[ma][na][0] + bias[col];
            float v1 = acc[ma][na][1] + bias[col + 1];
            float v2 = acc[ma][na][2] + bias[col];
            float v3 = acc[ma][na][3] + bias[col + 1];
            if (EPI == 2) {
                v0 += R[(size_t)row0 * N + col];     v1 += R[(size_t)row0 * N + col + 1];
                v2 += R[(size_t)row1 * N + col];     v3 += R[(size_t)row1 * N + col + 1];
            }
            if (EPI == 3) {
                v0 = 0.5f * v0 * (1.0f + erff(v0 * 0.70710678118654752f));
                v1 = 0.5f * v1 * (1.0f + erff(v1 * 0.70710678118654752f));
                v2 = 0.5f * v2 * (1.0f + erff(v2 * 0.70710678118654752f));
                v3 = 0.5f * v3 * (1.0f + erff(v3 * 0.70710678118654752f));
                __nv_bfloat162 h0, l0, h1, l1;
                h0.x = __float2bfloat16(v0); h0.y = __float2bfloat16(v1);
                l0.x = __float2bfloat16(v0 - __bfloat162float(h0.x));
                l0.y = __float2bfloat16(v1 - __bfloat162float(h0.y));
                h1.x = __float2bfloat16(v2); h1.y = __float2bfloat16(v3);
                l1.x = __float2bfloat16(v2 - __bfloat162float(h1.x));
                l1.y = __float2bfloat16(v3 - __bfloat162float(h1.y));
                __nv_bfloat16* c0 = Ce + (size_t)row0 * 3 * N;
                __nv_bfloat16* c1 = Ce + (size_t)row1 * 3 * N;
                *reinterpret_cast<__nv_bfloat162*>(c0 + col)         = h0;
                *reinterpret_cast<__nv_bfloat162*>(c0 + N + col)     = l0;
                *reinterpret_cast<__nv_bfloat162*>(c0 + 2 * N + col) = h0;
                *reinterpret_cast<__nv_bfloat162*>(c1 + col)         = h1;
                *reinterpret_cast<__nv_bfloat162*>(c1 + N + col)     = l1;
                *reinterpret_cast<__nv_bfloat162*>(c1 + 2 * N + col) = h1;
            } else {
                *reinterpret_cast<float2*>(Cf + (size_t)row0 * N + col) = make_float2(v0, v1);
                *reinterpret_cast<float2*>(Cf + (size_t)row1 * N + col) = make_float2(v2, v3);
            }
        }
    }
}

// ---------------------------------------------------------------------------
// Fused masked-causal attention (round-7 version: warp-per-query, shfl reduce)
// Output: expanded bf16 [hi|lo|hi] into Ye [row][3C].
// ---------------------------------------------------------------------------
__global__ __launch_bounds__(256)
void attn_kernel(const float* __restrict__ QKV, __nv_bfloat16* __restrict__ Ye)
{
    const int bh = blockIdx.x;
    const int b  = bh >> 4;
    const int h  = bh & 15;
    const int qbase = blockIdx.y * 8;
    const int warp = threadIdx.x >> 5;
    const int lane = threadIdx.x & 31;
    const int tq = qbase + warp;

    __shared__ float Ks[64][66];
    __shared__ float Vs[64][66];

    const size_t rq = (size_t)(b * T_SEQ + tq) * NQKV + h * HEAD_D;
    const float q0 = QKV[rq + lane * 2];
    const float q1 = QKV[rq + lane * 2 + 1];

    float m = -INFINITY, l = 0.f, acc0 = 0.f, acc1 = 0.f;
    const int smax = qbase + 7;

    for (int s0 = 0; s0 <= smax; s0 += 64) {
        const int tile = min(64, smax + 1 - s0);
        __syncthreads();
        for (int idx = threadIdx.x; idx < 64 * 64; idx += 256) {
            const int r = idx >> 6, cc = idx & 63;
            float kv = 0.f, vv = 0.f;
            if (r < tile) {
                const size_t g = (size_t)(b * T_SEQ + s0 + r) * NQKV + h * HEAD_D + cc;
                kv = QKV[g + C_DIM];
                vv = QKV[g + 2 * C_DIM];
            }
            Ks[r][cc] = kv; Vs[r][cc] = vv;
        }
        __syncthreads();

        const int send = min(tq, s0 + 63);
        for (int s = s0; s <= send; ++s) {
            if ((s & 15) == 15) continue;
            const int r = s - s0;
            float p = q0 * Ks[r][lane * 2] + q1 * Ks[r][lane * 2 + 1];
#pragma unroll
            for (int off = 16; off; off >>= 1) p += __shfl_xor_sync(~0u, p, off);
            p *= 0.125f;
            const float mnew = fmaxf(m, p);
            const float corr = __expf(m - mnew);
            const float wgt  = __expf(p - mnew);
            l    = l * corr + wgt;
            acc0 = acc0 * corr + wgt * Vs[r][lane * 2];
            acc1 = acc1 * corr + wgt * Vs[r][lane * 2 + 1];
            m = mnew;
        }
    }
    const float inv = 1.0f / l;
    const float o0 = acc0 * inv, o1 = acc1 * inv;

    const int row = b * T_SEQ + tq;
    const int c = h * HEAD_D + lane * 2;
    __nv_bfloat162 hi2, lo2;
    hi2.x = __float2bfloat16(o0); hi2.y = __float2bfloat16(o1);
    lo2.x = __float2bfloat16(o0 - __bfloat162float(hi2.x));
    lo2.y = __float2bfloat16(o1 - __bfloat162float(hi2.y));
    __nv_bfloat16* yr = Ye + (size_t)row * K3C;
    *reinterpret_cast<__nv_bfloat162*>(yr + c)             = hi2;
    *reinterpret_cast<__nv_bfloat162*>(yr + C_DIM + c)     = lo2;
    *reinterpret_cast<__nv_bfloat162*>(yr + 2 * C_DIM + c) = hi2;
}

// ---------------------------------------------------------------------------
// EinLinear head
// ---------------------------------------------------------------------------
__global__ __launch_bounds__(256)
void head_kernel(const float* __restrict__ X, const float* __restrict__ Wh,
                 float* __restrict__ out)
{
    const int e     = blockIdx.x & 15;
    const int chunk = blockIdx.x >> 4;
    const int tid = threadIdx.x;
    const int warp = tid >> 5, lane = tid & 31;

    __shared__ float xs[8][C_DIM];
    int rows[8];
#pragma unroll
    for (int j = 0; j < 8; ++j) rows[j] = (chunk * 8 + j) * TRANS + e;

#pragma unroll
    for (int j = 0; j < 8; ++j)
        for (int idx = tid; idx < C_DIM; idx += 256)
            xs[j][idx] = X[(size_t)rows[j] * C_DIM + idx];
    __syncthreads();

    for (int o = warp; o < VOCABP1; o += 8) {
        const float* w = Wh + ((size_t)e * VOCABP1 + o) * C_DIM;
        float a[8];
#pragma unroll
        for (int j = 0; j < 8; ++j) a[j] = 0.f;
        for (int k = lane; k < C_DIM; k += 32) {
            const float wv = w[k];
#pragma unroll
            for (int j = 0; j < 8; ++j) a[j] += wv * xs[j][k];
        }
#pragma unroll
        for (int j = 0; j < 8; ++j)
#pragma unroll
            for (int off = 16; off; off >>= 1)
                a[j] += __shfl_xor_sync(~0u, a[j], off);
        if (lane == 0) {
#pragma unroll
            for (int j = 0; j < 8; ++j)
                out[(size_t)rows[j] * VOCABP1 + o] = a[j];
        }
    }
}

// ---------------------------------------------------------------------------
// Launch
// ---------------------------------------------------------------------------
extern "C" void kernel_launch(void* const* d_in, const int* in_sizes, int n_in,
                              void* d_out, int out_size)
{
    const int*   tokens  = (const int*)  d_in[0];
    const float* tok_emb = (const float*)d_in[1];
    const float* pos_emb = (const float*)d_in[2];
    const float* Wq = (const float*)d_in[3];  const float* bq = (const float*)d_in[4];
    const float* Wk = (const float*)d_in[5];  const float* bk = (const float*)d_in[6];
    const float* Wv = (const float*)d_in[7];  const float* bv = (const float*)d_in[8];
    const float* Wp = (const float*)d_in[9];  const float* bp = (const float*)d_in[10];
    const float* ln1w = (const float*)d_in[11]; const float* ln1b = (const float*)d_in[12];
    const float* ln2w = (const float*)d_in[13]; const float* ln2b = (const float*)d_in[14];
    const float* W1 = (const float*)d_in[15]; const float* b1 = (const float*)d_in[16];
    const float* W2 = (const float*)d_in[17]; const float* b2 = (const float*)d_in[18];
    const float* lnfw = (const float*)d_in[19]; const float* lnfb = (const float*)d_in[20];
    const float* head_w = (const float*)d_in[21];

    float *x, *h, *qkv, *bqkv;
    __nv_bfloat16 *aC, *aF, *wqkvx, *wpx, *w1x, *w2x;
    cudaGetSymbolAddress((void**)&x,    g_x);
    cudaGetSymbolAddress((void**)&h,    g_h);
    cudaGetSymbolAddress((void**)&qkv,  g_qkv);
    cudaGetSymbolAddress((void**)&bqkv, g_bqkv);
    cudaGetSymbolAddress((void**)&aC,   g_aexpC);
    cudaGetSymbolAddress((void**)&aF,   g_aexpF);
    cudaGetSymbolAddress((void**)&wqkvx, g_wqkv);
    cudaGetSymbolAddress((void**)&wpx,  g_wp);
    cudaGetSymbolAddress((void**)&w1x,  g_w1);
    cudaGetSymbolAddress((void**)&w2x,  g_w2);

    cudaFuncSetAttribute(mma_gemm<1>, cudaFuncAttributeMaxDynamicSharedMemorySize, G_SMEM);
    cudaFuncSetAttribute(mma_gemm<2>, cudaFuncAttributeMaxDynamicSharedMemorySize, G_SMEM);
    cudaFuncSetAttribute(mma_gemm<3>, cudaFuncAttributeMaxDynamicSharedMemorySize, G_SMEM);

    const dim3 wb(32, 8);
    for (int i = 0; i < N_LAYER; ++i) {
        const size_t wc = (size_t)i * C_DIM * C_DIM;
        __nv_bfloat16* wl = wqkvx + (size_t)i * NQKV * K3C;
        expand_wT<<<dim3(32, 32), wb>>>(Wq + wc, wl,                           C_DIM, C_DIM);
        expand_wT<<<dim3(32, 32), wb>>>(Wk + wc, wl + (size_t)C_DIM * K3C,     C_DIM, C_DIM);
        expand_wT<<<dim3(32, 32), wb>>>(Wv + wc, wl + (size_t)2 * C_DIM * K3C, C_DIM, C_DIM);
        expand_wT<<<dim3(32, 32), wb>>>(Wp + wc, wpx + (size_t)i * C_DIM * K3C, C_DIM, C_DIM);
        expand_wT<<<dim3(32, 128), wb>>>(W1 + (size_t)i * C_DIM * F4_DIM,
                                         w1x + (size_t)i * F4_DIM * K3C, C_DIM, F4_DIM);
        expand_wT<<<dim3(128, 32), wb>>>(W2 + (size_t)i * F4_DIM * C_DIM,
                                         w2x + (size_t)i * C_DIM * K3F, F4_DIM, C_DIM);
    }
    bqkv_kernel<<<N_LAYER * NQKV / 256, 256>>>(bq, bk, bv, bqkv);

    embed_kernel<<<ROWS * C_DIM / 256, 256>>>(tokens, tok_emb, pos_emb, x);

    const dim3 gQKV(NQKV   / 128, ROWS / 128);
    const dim3 gC  (C_DIM  / 128, ROWS / 128);
    const dim3 gF4 (F4_DIM / 128, ROWS / 128);

    for (int i = 0; i < N_LAYER; ++i) {
        const size_t bc = (size_t)i * C_DIM;

        ln_kernel<1><<<ROWS, 256>>>(x, ln1w + bc, ln1b + bc, nullptr, aC);
        mma_gemm<1><<<gQKV, 256, G_SMEM>>>(aC, wqkvx + (size_t)i * NQKV * K3C,
                                           bqkv + (size_t)i * NQKV, nullptr,
                                           qkv, nullptr, NQKV, K3C);

        attn_kernel<<<dim3(B_SZ * N_HEADS, T_SEQ / 8), 256>>>(qkv, aC);

        mma_gemm<2><<<gC, 256, G_SMEM>>>(aC, wpx + (size_t)i * C_DIM * K3C,
                                         bp + bc, x, x, nullptr, C_DIM, K3C);

        ln_kernel<1><<<ROWS, 256>>>(x, ln2w + bc, ln2b + bc, nullptr, aC);
        mma_gemm<3><<<gF4, 256, G_SMEM>>>(aC, w1x + (size_t)i * F4_DIM * K3C,
                                          b1 + (size_t)i * F4_DIM, nullptr,
                                          nullptr, aF, F4_DIM, K3C);

        mma_gemm<2><<<gC, 256, G_SMEM>>>(aF, w2x + (size_t)i * C_DIM * K3F,
                                         b2 + bc, x, x, nullptr, C_DIM, K3F);
    }

    ln_kernel<0><<<ROWS, 256>>>(x, lnfw, lnfb, h, nullptr);
    head_kernel<<<256, 256>>>(h, head_w, (float*)d_out);
}

// round 10
// speedup vs baseline: 1.7329x; 1.2785x over previous
#include <cuda_runtime.h>
#include <cuda_bf16.h>
#include <cstdint>
#include <math.h>

// ---------------------------------------------------------------------------
// Model constants
// ---------------------------------------------------------------------------
#define N_LAYER 4
#define N_HEADS 16
#define C_DIM   1024
#define T_SEQ   1024
#define B_SZ    2
#define ROWS    (B_SZ * T_SEQ)      // 2048
#define F4_DIM  (4 * C_DIM)         // 4096
#define HEAD_D  64
#define VOCABP1 101
#define TRANS   16
#define K3C     (3 * C_DIM)         // 3072
#define K3F     (3 * F4_DIM)        // 12288
#define NQKV    (3 * C_DIM)         // 3072

// ---------------------------------------------------------------------------
// Static device scratch (no allocations allowed)
// ---------------------------------------------------------------------------
__device__ float g_x  [ROWS * C_DIM];
__device__ float g_h  [ROWS * C_DIM];
__device__ float g_qkv[ROWS * NQKV];

__device__ __nv_bfloat16 g_aexpC[(size_t)ROWS * K3C];
__device__ __nv_bfloat16 g_aexpF[(size_t)ROWS * K3F];

__device__ __nv_bfloat16 g_wqkv[(size_t)N_LAYER * NQKV * K3C];
__device__ __nv_bfloat16 g_wp  [(size_t)N_LAYER * C_DIM * K3C];
__device__ __nv_bfloat16 g_w1  [(size_t)N_LAYER * F4_DIM * K3C];
__device__ __nv_bfloat16 g_w2  [(size_t)N_LAYER * C_DIM * K3F];

// ---------------------------------------------------------------------------
// PTX helpers (sm_80-safe only; ptxas targets plain sm_103)
// ---------------------------------------------------------------------------
__device__ __forceinline__ uint32_t smem_u32(const void* p) {
    uint32_t a;
    asm("{ .reg .u64 t; cvta.to.shared.u64 t, %1; cvt.u32.u64 %0, t; }" : "=r"(a) : "l"(p));
    return a;
}
__device__ __forceinline__ void cp_async16(uint32_t s, const void* g) {
    asm volatile("cp.async.cg.shared.global [%0], [%1], 16;" :: "r"(s), "l"(g));
}
__device__ __forceinline__ void cp_commit() { asm volatile("cp.async.commit_group;"); }
template<int N> __device__ __forceinline__ void cp_wait() {
    asm volatile("cp.async.wait_group %0;" :: "n"(N));
}
__device__ __forceinline__ void ldsm_x4(uint32_t& r0, uint32_t& r1, uint32_t& r2, uint32_t& r3,
                                        uint32_t addr) {
    asm volatile("ldmatrix.sync.aligned.m8n8.x4.shared.b16 {%0,%1,%2,%3}, [%4];"
                 : "=r"(r0), "=r"(r1), "=r"(r2), "=r"(r3) : "r"(addr));
}
__device__ __forceinline__ void mma16816(float* c, const uint32_t* a, uint32_t b0, uint32_t b1) {
    asm volatile("mma.sync.aligned.m16n8k16.row.col.f32.bf16.bf16.f32 "
                 "{%0,%1,%2,%3}, {%4,%5,%6,%7}, {%8,%9}, {%0,%1,%2,%3};"
                 : "+f"(c[0]), "+f"(c[1]), "+f"(c[2]), "+f"(c[3])
                 : "r"(a[0]), "r"(a[1]), "r"(a[2]), "r"(a[3]), "r"(b0), "r"(b1));
}
__device__ __forceinline__ uint32_t swz(int r, int s8) {
    return (uint32_t)(r * 128 + ((s8 ^ (r & 7)) << 4));
}

// ---------------------------------------------------------------------------
// Embedding
// ---------------------------------------------------------------------------
__global__ void embed_kernel(const int* __restrict__ tokens,
                             const float* __restrict__ tok_emb,
                             const float* __restrict__ pos_emb,
                             float* __restrict__ X)
{
    int i = blockIdx.x * blockDim.x + threadIdx.x;
    int row = i >> 10;
    int c   = i & 1023;
    int t   = row & 1023;
    int tok = tokens[row];
    X[i] = tok_emb[(size_t)tok * C_DIM + c] + pos_emb[(size_t)t * C_DIM + c];
}

// ---------------------------------------------------------------------------
// LayerNorm. EXP=0: fp32 Y. EXP=1: bf16 [hi|lo|hi] into Ye [row][3C]
// ---------------------------------------------------------------------------
template<int EXP>
__global__ void ln_kernel(const float* __restrict__ X,
                          const float* __restrict__ w,
                          const float* __restrict__ b,
                          float* __restrict__ Y, __nv_bfloat16* __restrict__ Ye)
{
    const int row = blockIdx.x;
    const float* x = X + (size_t)row * C_DIM;
    const int tid = threadIdx.x;

    float v[4];
    float s = 0.f;
#pragma unroll
    for (int i = 0; i < 4; ++i) { v[i] = x[tid + 256 * i]; s += v[i]; }

    __shared__ float red[8];
#pragma unroll
    for (int off = 16; off; off >>= 1) s += __shfl_xor_sync(~0u, s, off);
    if ((tid & 31) == 0) red[tid >> 5] = s;
    __syncthreads();
    float tot = 0.f;
#pragma unroll
    for (int j = 0; j < 8; ++j) tot += red[j];
    const float mu = tot * (1.0f / C_DIM);
    __syncthreads();

    float ss = 0.f;
#pragma unroll
    for (int i = 0; i < 4; ++i) { float d = v[i] - mu; ss += d * d; }
#pragma unroll
    for (int off = 16; off; off >>= 1) ss += __shfl_xor_sync(~0u, ss, off);
    if ((tid & 31) == 0) red[tid >> 5] = ss;
    __syncthreads();
    float tot2 = 0.f;
#pragma unroll
    for (int j = 0; j < 8; ++j) tot2 += red[j];
    const float rs = rsqrtf(tot2 * (1.0f / C_DIM) + 1e-5f);

#pragma unroll
    for (int i = 0; i < 4; ++i) {
        const int c = tid + 256 * i;
        const float o = (v[i] - mu) * rs * w[c] + b[c];
        if (EXP == 0) {
            Y[(size_t)row * C_DIM + c] = o;
        } else {
            __nv_bfloat16 hi = __float2bfloat16(o);
            __nv_bfloat16 lo = __float2bfloat16(o - __bfloat162float(hi));
            __nv_bfloat16* yr = Ye + (size_t)row * K3C;
            yr[c]             = hi;
            yr[C_DIM + c]     = lo;
            yr[2 * C_DIM + c] = hi;
        }
    }
}

// ---------------------------------------------------------------------------
// Split+transpose weight W [K,N] -> bf16 B' [N, 3K] = [hi | hi | lo]
// Batched over layers via blockIdx.z.
// ---------------------------------------------------------------------------
__global__ void expand_wT(const float* __restrict__ W, __nv_bfloat16* __restrict__ out,
                          int K, int N, size_t wstride, size_t ostride)
{
    W   += (size_t)blockIdx.z * wstride;
    out += (size_t)blockIdx.z * ostride;
    __shared__ float t[32][33];
    const int k0 = blockIdx.x * 32, n0 = blockIdx.y * 32;
    const int tx = threadIdx.x, ty = threadIdx.y;
#pragma unroll
    for (int i = 0; i < 4; ++i)
        t[ty + 8 * i][tx] = W[(size_t)(k0 + ty + 8 * i) * N + n0 + tx];
    __syncthreads();
#pragma unroll
    for (int i = 0; i < 4; ++i) {
        int n = n0 + ty + 8 * i;
        int k = k0 + tx;
        float x = t[tx][ty + 8 * i];
        __nv_bfloat16 hi = __float2bfloat16(x);
        __nv_bfloat16 lo = __float2bfloat16(x - __bfloat162float(hi));
        size_t base = (size_t)n * 3 * K;
        out[base + k]         = hi;
        out[base + K + k]     = hi;
        out[base + 2 * K + k] = lo;
    }
}

// ---------------------------------------------------------------------------
// HMMA bf16 GEMM: 128x128 tile, BK=64, 8 warps, 3-stage cp.async.
// EPI: 1 = bias -> Cf; 2 = bias+residual -> Cf; 3 = bias+gelu -> Ce [hi|lo|hi]
//      4 = segmented bias (bias|biasK|biasV by 1024-col range) -> Cf
// ---------------------------------------------------------------------------
#define G_STAGES 3
#define G_TILEB  (128 * 128)
#define G_STAGEB (2 * G_TILEB)
#define G_SMEM   (G_STAGES * G_STAGEB)   // 98304

template<int EPI>
__global__ __launch_bounds__(256, 2)
void mma_gemm(const __nv_bfloat16* __restrict__ A, const __nv_bfloat16* __restrict__ B,
              const float* __restrict__ bias, const float* __restrict__ biasK,
              const float* __restrict__ biasV, const float* __restrict__ R,
              float* __restrict__ Cf, __nv_bfloat16* __restrict__ Ce,
              int N, int K3)
{
    extern __shared__ char smem[];
    const uint32_t sbase = smem_u32(smem);
    const int tid  = threadIdx.x;
    const int wid  = tid >> 5, lane = tid & 31;
    const int warp_m = wid >> 2, warp_n = wid & 3;
    const int bx = blockIdx.x, by = blockIdx.y;

    const char* Abase = (const char*)(A + (size_t)(by * 128) * K3);
    const char* Bbase = (const char*)(B + (size_t)(bx * 128) * K3);
    const size_t ldg = (size_t)K3 * 2;
    const int nchunks = K3 >> 6;

    const int r_cp[4] = { tid >> 3, (tid + 256) >> 3, (tid + 512) >> 3, (tid + 768) >> 3 };
    const int s8_cp   = tid & 7;

#pragma unroll
    for (int st = 0; st < G_STAGES - 1; ++st) {
        const uint32_t sb = sbase + st * G_STAGEB;
#pragma unroll
        for (int p = 0; p < 4; ++p) {
            const int r = r_cp[p];
            cp_async16(sb + swz(r, s8_cp),           Abase + (size_t)r * ldg + st * 128 + s8_cp * 16);
            cp_async16(sb + G_TILEB + swz(r, s8_cp), Bbase + (size_t)r * ldg + st * 128 + s8_cp * 16);
        }
        cp_commit();
    }

    float acc[4][4][4];
#pragma unroll
    for (int i = 0; i < 4; ++i)
#pragma unroll
        for (int j = 0; j < 4; ++j)
#pragma unroll
            for (int r = 0; r < 4; ++r) acc[i][j][r] = 0.f;

    const int a_r0 = warp_m * 64 + (lane & 15);
    const int a_s0 = lane >> 4;
    const int b_r0 = warp_n * 32 + (lane & 7) + ((lane >> 4) << 3);
    const int b_s0 = (lane >> 3) & 1;

    for (int c = 0; c < nchunks; ++c) {
        cp_wait<G_STAGES - 2>();
        __syncthreads();

        const int nc = c + G_STAGES - 1;
        if (nc < nchunks) {
            const uint32_t nb = sbase + (nc % G_STAGES) * G_STAGEB;
#pragma unroll
            for (int p = 0; p < 4; ++p) {
                const int r = r_cp[p];
                cp_async16(nb + swz(r, s8_cp),           Abase + (size_t)r * ldg + nc * 128 + s8_cp * 16);
                cp_async16(nb + G_TILEB + swz(r, s8_cp), Bbase + (size_t)r * ldg + nc * 128 + s8_cp * 16);
            }
        }
        cp_commit();

        const uint32_t sb = sbase + (c % G_STAGES) * G_STAGEB;
#pragma unroll
        for (int ks = 0; ks < 4; ++ks) {
            uint32_t af[4][4], bfr[2][4];
#pragma unroll
            for (int ma = 0; ma < 4; ++ma) {
                const int r = a_r0 + ma * 16;
                ldsm_x4(af[ma][0], af[ma][1], af[ma][2], af[ma][3],
                        sb + swz(r, ks * 2 + a_s0));
            }
#pragma unroll
            for (int j = 0; j < 2; ++j) {
                const int r = b_r0 + j * 16;
                ldsm_x4(bfr[j][0], bfr[j][1], bfr[j][2], bfr[j][3],
                        sb + G_TILEB + swz(r, ks * 2 + b_s0));
            }
#pragma unroll
            for (int ma = 0; ma < 4; ++ma)
#pragma unroll
                for (int na = 0; na < 4; ++na)
                    mma16816(acc[ma][na], af[ma], bfr[na >> 1][(na & 1) * 2],
                             bfr[na >> 1][(na & 1) * 2 + 1]);
        }
    }

    // epilogue
#pragma unroll
    for (int ma = 0; ma < 4; ++ma) {
        const int row0 = by * 128 + warp_m * 64 + ma * 16 + (lane >> 2);
        const int row1 = row0 + 8;
#pragma unroll
        for (int na = 0; na < 4; ++na) {
            const int col = bx * 128 + warp_n * 32 + na * 8 + (lane & 3) * 2;
            float b0, b1;
            if (EPI == 4) {
                b0 = (col < C_DIM) ? bias[col]
                   : (col < 2 * C_DIM) ? biasK[col - C_DIM] : biasV[col - 2 * C_DIM];
                b1 = (col + 1 < C_DIM) ? bias[col + 1]
                   : (col + 1 < 2 * C_DIM) ? biasK[col + 1 - C_DIM] : biasV[col + 1 - 2 * C_DIM];
            } else {
                b0 = bias[col]; b1 = bias[col + 1];
            }
            float v0 = acc[ma][na][0] + b0;
            float v1 = acc[ma][na][1] + b1;
            float v2 = acc[ma][na][2] + b0;
            float v3 = acc[ma][na][3] + b1;
            if (EPI == 2) {
                v0 += R[(size_t)row0 * N + col];     v1 += R[(size_t)row0 * N + col + 1];
                v2 += R[(size_t)row1 * N + col];     v3 += R[(size_t)row1 * N + col + 1];
            }
            if (EPI == 3) {
                v0 = 0.5f * v0 * (1.0f + erff(v0 * 0.70710678118654752f));
                v1 = 0.5f * v1 * (1.0f + erff(v1 * 0.70710678118654752f));
                v2 = 0.5f * v2 * (1.0f + erff(v2 * 0.70710678118654752f));
                v3 = 0.5f * v3 * (1.0f + erff(v3 * 0.70710678118654752f));
                __nv_bfloat162 h0, l0, h1, l1;
                h0.x = __float2bfloat16(v0); h0.y = __float2bfloat16(v1);
                l0.x = __float2bfloat16(v0 - __bfloat162float(h0.x));
                l0.y = __float2bfloat16(v1 - __bfloat162float(h0.y));
                h1.x = __float2bfloat16(v2); h1.y = __float2bfloat16(v3);
                l1.x = __float2bfloat16(v2 - __bfloat162float(h1.x));
                l1.y = __float2bfloat16(v3 - __bfloat162float(h1.y));
                __nv_bfloat16* c0 = Ce + (size_t)row0 * 3 * N;
                __nv_bfloat16* c1 = Ce + (size_t)row1 * 3 * N;
                *reinterpret_cast<__nv_bfloat162*>(c0 + col)         = h0;
                *reinterpret_cast<__nv_bfloat162*>(c0 + N + col)     = l0;
                *reinterpret_cast<__nv_bfloat162*>(c0 + 2 * N + col) = h0;
                *reinterpret_cast<__nv_bfloat162*>(c1 + col)         = h1;
                *reinterpret_cast<__nv_bfloat162*>(c1 + N + col)     = l1;
                *reinterpret_cast<__nv_bfloat162*>(c1 + 2 * N + col) = h1;
            } else {
                *reinterpret_cast<float2*>(Cf + (size_t)row0 * N + col) = make_float2(v0, v1);
                *reinterpret_cast<float2*>(Cf + (size_t)row1 * N + col) = make_float2(v2, v3);
            }
        }
    }
}

// ---------------------------------------------------------------------------
// Fused masked-causal attention, 4-way key batching.
// warp <-> one query row; per group of 4 keys: 4 independent shfl-reduction
// chains (latency overlapped) + ONE softmax state update.
// K/V tiles padded to 68 rows, zero-filled, so over-read rows are exact 0.
// Output: expanded bf16 [hi|lo|hi] into Ye [row][3C].
// ---------------------------------------------------------------------------
__global__ __launch_bounds__(256)
void attn_kernel(const float* __restrict__ QKV, __nv_bfloat16* __restrict__ Ye)
{
    const int bh = blockIdx.x;
    const int b  = bh >> 4;
    const int h  = bh & 15;
    const int qbase = blockIdx.y * 8;
    const int warp = threadIdx.x >> 5;
    const int lane = threadIdx.x & 31;
    const int tq = qbase + warp;

    __shared__ float Ks[68][66];
    __shared__ float Vs[68][66];

    const size_t rq = (size_t)(b * T_SEQ + tq) * NQKV + h * HEAD_D;
    const float q0 = QKV[rq + lane * 2];
    const float q1 = QKV[rq + lane * 2 + 1];

    float m = -INFINITY, l = 0.f, acc0 = 0.f, acc1 = 0.f;
    const int smax = qbase + 7;

    for (int s0 = 0; s0 <= smax; s0 += 64) {
        const int tile = min(64, smax + 1 - s0);
        __syncthreads();
        for (int idx = threadIdx.x; idx < 68 * 64; idx += 256) {
            const int r = idx >> 6, cc = idx & 63;
            float kv = 0.f, vv = 0.f;
            if (r < tile) {
                const size_t g = (size_t)(b * T_SEQ + s0 + r) * NQKV + h * HEAD_D + cc;
                kv = QKV[g + C_DIM];
                vv = QKV[g + 2 * C_DIM];
            }
            Ks[r][cc] = kv; Vs[r][cc] = vv;
        }
        __syncthreads();

        const int rend = min(tq, s0 + 63) - s0;      // last valid r
        for (int r = 0; r <= rend; r += 4) {
            float p[4];
#pragma unroll
            for (int j = 0; j < 4; ++j)
                p[j] = q0 * Ks[r + j][lane * 2] + q1 * Ks[r + j][lane * 2 + 1];
#pragma unroll
            for (int off = 16; off; off >>= 1) {
#pragma unroll
                for (int j = 0; j < 4; ++j)
                    p[j] += __shfl_xor_sync(~0u, p[j], off);
            }
#pragma unroll
            for (int j = 0; j < 4; ++j) {
                const int s = s0 + r + j;
                const bool valid = (s <= tq) && ((s & 15) != 15);
                p[j] = valid ? p[j] * 0.125f : -INFINITY;
            }
            const float mnew = fmaxf(fmaxf(fmaxf(p[0], p[1]), fmaxf(p[2], p[3])), m);
            const float corr = __expf(m - mnew);     // finite: p[0] always valid
            const float w0 = __expf(p[0] - mnew);
            const float w1 = __expf(p[1] - mnew);
            const float w2 = __expf(p[2] - mnew);
            const float w3 = __expf(p[3] - mnew);
            l = l * corr + ((w0 + w1) + (w2 + w3));
            acc0 = acc0 * corr + w0 * Vs[r][lane * 2]     + w1 * Vs[r + 1][lane * 2]
                               + w2 * Vs[r + 2][lane * 2] + w3 * Vs[r + 3][lane * 2];
            acc1 = acc1 * corr + w0 * Vs[r][lane * 2 + 1]     + w1 * Vs[r + 1][lane * 2 + 1]
                               + w2 * Vs[r + 2][lane * 2 + 1] + w3 * Vs[r + 3][lane * 2 + 1];
            m = mnew;
        }
    }
    const float inv = 1.0f / l;
    const float o0 = acc0 * inv, o1 = acc1 * inv;

    const int row = b * T_SEQ + tq;
    const int c = h * HEAD_D + lane * 2;
    __nv_bfloat162 hi2, lo2;
    hi2.x = __float2bfloat16(o0); hi2.y = __float2bfloat16(o1);
    lo2.x = __float2bfloat16(o0 - __bfloat162float(hi2.x));
    lo2.y = __float2bfloat16(o1 - __bfloat162float(hi2.y));
    __nv_bfloat16* yr = Ye + (size_t)row * K3C;
    *reinterpret_cast<__nv_bfloat162*>(yr + c)             = hi2;
    *reinterpret_cast<__nv_bfloat162*>(yr + C_DIM + c)     = lo2;
    *reinterpret_cast<__nv_bfloat162*>(yr + 2 * C_DIM + c) = hi2;
}

// ---------------------------------------------------------------------------
// EinLinear head
// ---------------------------------------------------------------------------
__global__ __launch_bounds__(256)
void head_kernel(const float* __restrict__ X, const float* __restrict__ Wh,
                 float* __restrict__ out)
{
    const int e     = blockIdx.x & 15;
    const int chunk = blockIdx.x >> 4;
    const int tid = threadIdx.x;
    const int warp = tid >> 5, lane = tid & 31;

    __shared__ float xs[8][C_DIM];
    int rows[8];
#pragma unroll
    for (int j = 0; j < 8; ++j) rows[j] = (chunk * 8 + j) * TRANS + e;

#pragma unroll
    for (int j = 0; j < 8; ++j)
        for (int idx = tid; idx < C_DIM; idx += 256)
            xs[j][idx] = X[(size_t)rows[j] * C_DIM + idx];
    __syncthreads();

    for (int o = warp; o < VOCABP1; o += 8) {
        const float* w = Wh + ((size_t)e * VOCABP1 + o) * C_DIM;
        float a[8];
#pragma unroll
        for (int j = 0; j < 8; ++j) a[j] = 0.f;
        for (int k = lane; k < C_DIM; k += 32) {
            const float wv = w[k];
#pragma unroll
            for (int j = 0; j < 8; ++j) a[j] += wv * xs[j][k];
        }
#pragma unroll
        for (int j = 0; j < 8; ++j)
#pragma unroll
            for (int off = 16; off; off >>= 1)
                a[j] += __shfl_xor_sync(~0u, a[j], off);
        if (lane == 0) {
#pragma unroll
            for (int j = 0; j < 8; ++j)
                out[(size_t)rows[j] * VOCABP1 + o] = a[j];
        }
    }
}

// ---------------------------------------------------------------------------
// Launch. Order chosen so the layer-0 QKV GEMM is launch #6 (ncu -s 5 -c 1).
// ---------------------------------------------------------------------------
extern "C" void kernel_launch(void* const* d_in, const int* in_sizes, int n_in,
                              void* d_out, int out_size)
{
    const int*   tokens  = (const int*)  d_in[0];
    const float* tok_emb = (const float*)d_in[1];
    const float* pos_emb = (const float*)d_in[2];
    const float* Wq = (const float*)d_in[3];  const float* bq = (const float*)d_in[4];
    const float* Wk = (const float*)d_in[5];  const float* bk = (const float*)d_in[6];
    const float* Wv = (const float*)d_in[7];  const float* bv = (const float*)d_in[8];
    const float* Wp = (const float*)d_in[9];  const float* bp = (const float*)d_in[10];
    const float* ln1w = (const float*)d_in[11]; const float* ln1b = (const float*)d_in[12];
    const float* ln2w = (const float*)d_in[13]; const float* ln2b = (const float*)d_in[14];
    const float* W1 = (const float*)d_in[15]; const float* b1 = (const float*)d_in[16];
    const float* W2 = (const float*)d_in[17]; const float* b2 = (const float*)d_in[18];
    const float* lnfw = (const float*)d_in[19]; const float* lnfb = (const float*)d_in[20];
    const float* head_w = (const float*)d_in[21];

    float *x, *h, *qkv;
    __nv_bfloat16 *aC, *aF, *wqkvx, *wpx, *w1x, *w2x;
    cudaGetSymbolAddress((void**)&x,    g_x);
    cudaGetSymbolAddress((void**)&h,    g_h);
    cudaGetSymbolAddress((void**)&qkv,  g_qkv);
    cudaGetSymbolAddress((void**)&aC,   g_aexpC);
    cudaGetSymbolAddress((void**)&aF,   g_aexpF);
    cudaGetSymbolAddress((void**)&wqkvx, g_wqkv);
    cudaGetSymbolAddress((void**)&wpx,  g_wp);
    cudaGetSymbolAddress((void**)&w1x,  g_w1);
    cudaGetSymbolAddress((void**)&w2x,  g_w2);

    cudaFuncSetAttribute(mma_gemm<1>, cudaFuncAttributeMaxDynamicSharedMemorySize, G_SMEM);
    cudaFuncSetAttribute(mma_gemm<2>, cudaFuncAttributeMaxDynamicSharedMemorySize, G_SMEM);
    cudaFuncSetAttribute(mma_gemm<3>, cudaFuncAttributeMaxDynamicSharedMemorySize, G_SMEM);
    cudaFuncSetAttribute(mma_gemm<4>, cudaFuncAttributeMaxDynamicSharedMemorySize, G_SMEM);

    const dim3 wb(32, 8);
    const dim3 gQKV(NQKV   / 128, ROWS / 128);
    const dim3 gC  (C_DIM  / 128, ROWS / 128);
    const dim3 gF4 (F4_DIM / 128, ROWS / 128);
    const dim3 gAtt(B_SZ * N_HEADS, T_SEQ / 8);

    // launches 1-3: QKV weight expansion (all layers, z-batched)
    expand_wT<<<dim3(32, 32, N_LAYER), wb>>>(Wq, wqkvx,
        C_DIM, C_DIM, (size_t)C_DIM * C_DIM, (size_t)NQKV * K3C);
    expand_wT<<<dim3(32, 32, N_LAYER), wb>>>(Wk, wqkvx + (size_t)C_DIM * K3C,
        C_DIM, C_DIM, (size_t)C_DIM * C_DIM, (size_t)NQKV * K3C);
    expand_wT<<<dim3(32, 32, N_LAYER), wb>>>(Wv, wqkvx + (size_t)2 * C_DIM * K3C,
        C_DIM, C_DIM, (size_t)C_DIM * C_DIM, (size_t)NQKV * K3C);
    // launch 4: embedding
    embed_kernel<<<ROWS * C_DIM / 256, 256>>>(tokens, tok_emb, pos_emb, x);
    // launch 5: layer-0 ln1
    ln_kernel<1><<<ROWS, 256>>>(x, ln1w, ln1b, nullptr, aC);
    // launch 6: layer-0 QKV GEMM  <-- ncu profiles this one
    mma_gemm<4><<<gQKV, 256, G_SMEM>>>(aC, wqkvx, bq, bk, bv, nullptr,
                                       qkv, nullptr, NQKV, K3C);

    // remaining weight expansions (needed before proj/W1/W2 of layer 0)
    expand_wT<<<dim3(32, 32, N_LAYER), wb>>>(Wp, wpx,
        C_DIM, C_DIM, (size_t)C_DIM * C_DIM, (size_t)C_DIM * K3C);
    expand_wT<<<dim3(32, 128, N_LAYER), wb>>>(W1, w1x,
        C_DIM, F4_DIM, (size_t)C_DIM * F4_DIM, (size_t)F4_DIM * K3C);
    expand_wT<<<dim3(128, 32, N_LAYER), wb>>>(W2, w2x,
        F4_DIM, C_DIM, (size_t)F4_DIM * C_DIM, (size_t)C_DIM * K3F);

    for (int i = 0; i < N_LAYER; ++i) {
        const size_t bc = (size_t)i * C_DIM;

        if (i > 0) {
            ln_kernel<1><<<ROWS, 256>>>(x, ln1w + bc, ln1b + bc, nullptr, aC);
            mma_gemm<4><<<gQKV, 256, G_SMEM>>>(aC, wqkvx + (size_t)i * NQKV * K3C,
                                               bq + bc, bk + bc, bv + bc, nullptr,
                                               qkv, nullptr, NQKV, K3C);
        }

        attn_kernel<<<gAtt, 256>>>(qkv, aC);

        mma_gemm<2><<<gC, 256, G_SMEM>>>(aC, wpx + (size_t)i * C_DIM * K3C,
                                         bp + bc, nullptr, nullptr, x,
                                         x, nullptr, C_DIM, K3C);

        ln_kernel<1><<<ROWS, 256>>>(x, ln2w + bc, ln2b + bc, nullptr, aC);
        mma_gemm<3><<<gF4, 256, G_SMEM>>>(aC, w1x + (size_t)i * F4_DIM * K3C,
                                          b1 + (size_t)i * F4_DIM, nullptr, nullptr, nullptr,
                                          nullptr, aF, F4_DIM, K3C);

        mma_gemm<2><<<gC, 256, G_SMEM>>>(aF, w2x + (size_t)i * C_DIM * K3F,
                                         b2 + bc, nullptr, nullptr, x,
                                         x, nullptr, C_DIM, K3F);
    }

    ln_kernel<0><<<ROWS, 256>>>(x, lnfw, lnfb, h, nullptr);
    head_kernel<<<256, 256>>>(h, head_w, (float*)d_out);
}

// round 11
// speedup vs baseline: 1.7497x; 1.0097x over previous
#include <cuda_runtime.h>
#include <cuda_bf16.h>
#include <cstdint>
#include <math.h>

// ---------------------------------------------------------------------------
// Model constants
// ---------------------------------------------------------------------------
#define N_LAYER 4
#define N_HEADS 16
#define C_DIM   1024
#define T_SEQ   1024
#define B_SZ    2
#define ROWS    (B_SZ * T_SEQ)      // 2048
#define F4_DIM  (4 * C_DIM)         // 4096
#define HEAD_D  64
#define VOCABP1 101
#define TRANS   16
#define K3C     (3 * C_DIM)         // 3072
#define K3F     (3 * F4_DIM)        // 12288
#define NQKV    (3 * C_DIM)         // 3072

// ---------------------------------------------------------------------------
// Static device scratch (no allocations allowed)
// ---------------------------------------------------------------------------
__device__ float g_x   [ROWS * C_DIM];
__device__ float g_h   [ROWS * C_DIM];
__device__ float g_qkv [ROWS * NQKV];
__device__ float g_part[2 * ROWS * C_DIM];            // split-K partials

__device__ __nv_bfloat16 g_aexpC[(size_t)ROWS * K3C];
__device__ __nv_bfloat16 g_aexpF[(size_t)ROWS * K3F];

__device__ __nv_bfloat16 g_wqkv[(size_t)N_LAYER * NQKV * K3C];
__device__ __nv_bfloat16 g_wp  [(size_t)N_LAYER * C_DIM * K3C];
__device__ __nv_bfloat16 g_w1  [(size_t)N_LAYER * F4_DIM * K3C];
__device__ __nv_bfloat16 g_w2  [(size_t)N_LAYER * C_DIM * K3F];

// ---------------------------------------------------------------------------
// PTX helpers (sm_80-safe only; ptxas targets plain sm_103)
// ---------------------------------------------------------------------------
__device__ __forceinline__ uint32_t smem_u32(const void* p) {
    uint32_t a;
    asm("{ .reg .u64 t; cvta.to.shared.u64 t, %1; cvt.u32.u64 %0, t; }" : "=r"(a) : "l"(p));
    return a;
}
__device__ __forceinline__ void cp_async16(uint32_t s, const void* g) {
    asm volatile("cp.async.cg.shared.global [%0], [%1], 16;" :: "r"(s), "l"(g));
}
__device__ __forceinline__ void cp_commit() { asm volatile("cp.async.commit_group;"); }
template<int N> __device__ __forceinline__ void cp_wait() {
    asm volatile("cp.async.wait_group %0;" :: "n"(N));
}
__device__ __forceinline__ void ldsm_x4(uint32_t& r0, uint32_t& r1, uint32_t& r2, uint32_t& r3,
                                        uint32_t addr) {
    asm volatile("ldmatrix.sync.aligned.m8n8.x4.shared.b16 {%0,%1,%2,%3}, [%4];"
                 : "=r"(r0), "=r"(r1), "=r"(r2), "=r"(r3) : "r"(addr));
}
__device__ __forceinline__ void mma16816(float* c, const uint32_t* a, uint32_t b0, uint32_t b1) {
    asm volatile("mma.sync.aligned.m16n8k16.row.col.f32.bf16.bf16.f32 "
                 "{%0,%1,%2,%3}, {%4,%5,%6,%7}, {%8,%9}, {%0,%1,%2,%3};"
                 : "+f"(c[0]), "+f"(c[1]), "+f"(c[2]), "+f"(c[3])
                 : "r"(a[0]), "r"(a[1]), "r"(a[2]), "r"(a[3]), "r"(b0), "r"(b1));
}
__device__ __forceinline__ uint32_t swz(int r, int s8) {
    return (uint32_t)(r * 128 + ((s8 ^ (r & 7)) << 4));
}

// ---------------------------------------------------------------------------
// Embedding
// ---------------------------------------------------------------------------
__global__ void embed_kernel(const int* __restrict__ tokens,
                             const float* __restrict__ tok_emb,
                             const float* __restrict__ pos_emb,
                             float* __restrict__ X)
{
    int i = blockIdx.x * blockDim.x + threadIdx.x;
    int row = i >> 10;
    int c   = i & 1023;
    int t   = row & 1023;
    int tok = tokens[row];
    X[i] = tok_emb[(size_t)tok * C_DIM + c] + pos_emb[(size_t)t * C_DIM + c];
}

// ---------------------------------------------------------------------------
// LayerNorm. EXP=0: fp32 Y. EXP=1: bf16 [hi|lo|hi] into Ye [row][3C]
// ---------------------------------------------------------------------------
template<int EXP>
__global__ void ln_kernel(const float* __restrict__ X,
                          const float* __restrict__ w,
                          const float* __restrict__ b,
                          float* __restrict__ Y, __nv_bfloat16* __restrict__ Ye)
{
    const int row = blockIdx.x;
    const float* x = X + (size_t)row * C_DIM;
    const int tid = threadIdx.x;

    float v[4];
    float s = 0.f;
#pragma unroll
    for (int i = 0; i < 4; ++i) { v[i] = x[tid + 256 * i]; s += v[i]; }

    __shared__ float red[8];
#pragma unroll
    for (int off = 16; off; off >>= 1) s += __shfl_xor_sync(~0u, s, off);
    if ((tid & 31) == 0) red[tid >> 5] = s;
    __syncthreads();
    float tot = 0.f;
#pragma unroll
    for (int j = 0; j < 8; ++j) tot += red[j];
    const float mu = tot * (1.0f / C_DIM);
    __syncthreads();

    float ss = 0.f;
#pragma unroll
    for (int i = 0; i < 4; ++i) { float d = v[i] - mu; ss += d * d; }
#pragma unroll
    for (int off = 16; off; off >>= 1) ss += __shfl_xor_sync(~0u, ss, off);
    if ((tid & 31) == 0) red[tid >> 5] = ss;
    __syncthreads();
    float tot2 = 0.f;
#pragma unroll
    for (int j = 0; j < 8; ++j) tot2 += red[j];
    const float rs = rsqrtf(tot2 * (1.0f / C_DIM) + 1e-5f);

#pragma unroll
    for (int i = 0; i < 4; ++i) {
        const int c = tid + 256 * i;
        const float o = (v[i] - mu) * rs * w[c] + b[c];
        if (EXP == 0) {
            Y[(size_t)row * C_DIM + c] = o;
        } else {
            __nv_bfloat16 hi = __float2bfloat16(o);
            __nv_bfloat16 lo = __float2bfloat16(o - __bfloat162float(hi));
            __nv_bfloat16* yr = Ye + (size_t)row * K3C;
            yr[c]             = hi;
            yr[C_DIM + c]     = lo;
            yr[2 * C_DIM + c] = hi;
        }
    }
}

// ---------------------------------------------------------------------------
// Split+transpose weight W [K,N] -> bf16 B' [N, 3K] = [hi | hi | lo]
// Batched over layers via blockIdx.z.
// ---------------------------------------------------------------------------
__global__ void expand_wT(const float* __restrict__ W, __nv_bfloat16* __restrict__ out,
                          int K, int N, size_t wstride, size_t ostride)
{
    W   += (size_t)blockIdx.z * wstride;
    out += (size_t)blockIdx.z * ostride;
    __shared__ float t[32][33];
    const int k0 = blockIdx.x * 32, n0 = blockIdx.y * 32;
    const int tx = threadIdx.x, ty = threadIdx.y;
#pragma unroll
    for (int i = 0; i < 4; ++i)
        t[ty + 8 * i][tx] = W[(size_t)(k0 + ty + 8 * i) * N + n0 + tx];
    __syncthreads();
#pragma unroll
    for (int i = 0; i < 4; ++i) {
        int n = n0 + ty + 8 * i;
        int k = k0 + tx;
        float x = t[tx][ty + 8 * i];
        __nv_bfloat16 hi = __float2bfloat16(x);
        __nv_bfloat16 lo = __float2bfloat16(x - __bfloat162float(hi));
        size_t base = (size_t)n * 3 * K;
        out[base + k]         = hi;
        out[base + K + k]     = hi;
        out[base + 2 * K + k] = lo;
    }
}

// ---------------------------------------------------------------------------
// split-K reduce: X[i] += P0[i] + P1[i] + bias[col]   (float4)
// ---------------------------------------------------------------------------
__global__ void reduce2_kernel(const float4* __restrict__ P,
                               const float4* __restrict__ bias,
                               float4* __restrict__ X)
{
    const int i = blockIdx.x * blockDim.x + threadIdx.x;   // over ROWS*C_DIM/4
    const int col4 = i & (C_DIM / 4 - 1);
    float4 a = P[i];
    float4 b = P[i + ROWS * C_DIM / 4];
    float4 bb = bias[col4];
    float4 xo = X[i];
    xo.x += a.x + b.x + bb.x;
    xo.y += a.y + b.y + bb.y;
    xo.z += a.z + b.z + bb.z;
    xo.w += a.w + b.w + bb.w;
    X[i] = xo;
}

// ---------------------------------------------------------------------------
// HMMA bf16 GEMM: 128x128 tile, BK=64, 8 warps, 3-stage cp.async.
// Split-K via gridDim.z: CTA z handles K columns [z*Ksub, (z+1)*Ksub).
// EPI: 0 = raw fp32 partial -> Cf + z*ROWS*N (no bias)
//      1 = bias -> Cf; 2 = bias+residual -> Cf; 3 = bias+gelu -> Ce [hi|lo|hi]
//      4 = segmented bias (bias|biasK|biasV by 1024-col range) -> Cf
// ---------------------------------------------------------------------------
#define G_STAGES 3
#define G_TILEB  (128 * 128)
#define G_STAGEB (2 * G_TILEB)
#define G_SMEM   (G_STAGES * G_STAGEB)   // 98304

template<int EPI>
__global__ __launch_bounds__(256, 2)
void mma_gemm(const __nv_bfloat16* __restrict__ A, const __nv_bfloat16* __restrict__ B,
              const float* __restrict__ bias, const float* __restrict__ biasK,
              const float* __restrict__ biasV, const float* __restrict__ R,
              float* __restrict__ Cf, __nv_bfloat16* __restrict__ Ce,
              int N, int Kfull, int Ksub)
{
    extern __shared__ char smem[];
    const uint32_t sbase = smem_u32(smem);
    const int tid  = threadIdx.x;
    const int wid  = tid >> 5, lane = tid & 31;
    const int warp_m = wid >> 2, warp_n = wid & 3;
    const int bx = blockIdx.x, by = blockIdx.y, bz = blockIdx.z;

    const char* Abase = (const char*)(A + (size_t)(by * 128) * Kfull + (size_t)bz * Ksub);
    const char* Bbase = (const char*)(B + (size_t)(bx * 128) * Kfull + (size_t)bz * Ksub);
    const size_t ldg = (size_t)Kfull * 2;
    const int nchunks = Ksub >> 6;

    const int r_cp[4] = { tid >> 3, (tid + 256) >> 3, (tid + 512) >> 3, (tid + 768) >> 3 };
    const int s8_cp   = tid & 7;

#pragma unroll
    for (int st = 0; st < G_STAGES - 1; ++st) {
        const uint32_t sb = sbase + st * G_STAGEB;
#pragma unroll
        for (int p = 0; p < 4; ++p) {
            const int r = r_cp[p];
            cp_async16(sb + swz(r, s8_cp),           Abase + (size_t)r * ldg + st * 128 + s8_cp * 16);
            cp_async16(sb + G_TILEB + swz(r, s8_cp), Bbase + (size_t)r * ldg + st * 128 + s8_cp * 16);
        }
        cp_commit();
    }

    float acc[4][4][4];
#pragma unroll
    for (int i = 0; i < 4; ++i)
#pragma unroll
        for (int j = 0; j < 4; ++j)
#pragma unroll
            for (int r = 0; r < 4; ++r) acc[i][j][r] = 0.f;

    const int a_r0 = warp_m * 64 + (lane & 15);
    const int a_s0 = lane >> 4;
    const int b_r0 = warp_n * 32 + (lane & 7) + ((lane >> 4) << 3);
    const int b_s0 = (lane >> 3) & 1;

    for (int c = 0; c < nchunks; ++c) {
        cp_wait<G_STAGES - 2>();
        __syncthreads();

        const int nc = c + G_STAGES - 1;
        if (nc < nchunks) {
            const uint32_t nb = sbase + (nc % G_STAGES) * G_STAGEB;
#pragma unroll
            for (int p = 0; p < 4; ++p) {
                const int r = r_cp[p];
                cp_async16(nb + swz(r, s8_cp),           Abase + (size_t)r * ldg + nc * 128 + s8_cp * 16);
                cp_async16(nb + G_TILEB + swz(r, s8_cp), Bbase + (size_t)r * ldg + nc * 128 + s8_cp * 16);
            }
        }
        cp_commit();

        const uint32_t sb = sbase + (c % G_STAGES) * G_STAGEB;
#pragma unroll
        for (int ks = 0; ks < 4; ++ks) {
            uint32_t af[4][4], bfr[2][4];
#pragma unroll
            for (int ma = 0; ma < 4; ++ma) {
                const int r = a_r0 + ma * 16;
                ldsm_x4(af[ma][0], af[ma][1], af[ma][2], af[ma][3],
                        sb + swz(r, ks * 2 + a_s0));
            }
#pragma unroll
            for (int j = 0; j < 2; ++j) {
                const int r = b_r0 + j * 16;
                ldsm_x4(bfr[j][0], bfr[j][1], bfr[j][2], bfr[j][3],
                        sb + G_TILEB + swz(r, ks * 2 + b_s0));
            }
#pragma unroll
            for (int ma = 0; ma < 4; ++ma)
#pragma unroll
                for (int na = 0; na < 4; ++na)
                    mma16816(acc[ma][na], af[ma], bfr[na >> 1][(na & 1) * 2],
                             bfr[na >> 1][(na & 1) * 2 + 1]);
        }
    }

    // epilogue
    float* Cout = (EPI == 0) ? (Cf + (size_t)bz * ROWS * N) : Cf;
#pragma unroll
    for (int ma = 0; ma < 4; ++ma) {
        const int row0 = by * 128 + warp_m * 64 + ma * 16 + (lane >> 2);
        const int row1 = row0 + 8;
#pragma unroll
        for (int na = 0; na < 4; ++na) {
            const int col = bx * 128 + warp_n * 32 + na * 8 + (lane & 3) * 2;
            if (EPI == 0) {
                *reinterpret_cast<float2*>(Cout + (size_t)row0 * N + col) =
                    make_float2(acc[ma][na][0], acc[ma][na][1]);
                *reinterpret_cast<float2*>(Cout + (size_t)row1 * N + col) =
                    make_float2(acc[ma][na][2], acc[ma][na][3]);
                continue;
            }
            float b0, b1;
            if (EPI == 4) {
                b0 = (col < C_DIM) ? bias[col]
                   : (col < 2 * C_DIM) ? biasK[col - C_DIM] : biasV[col - 2 * C_DIM];
                b1 = (col + 1 < C_DIM) ? bias[col + 1]
                   : (col + 1 < 2 * C_DIM) ? biasK[col + 1 - C_DIM] : biasV[col + 1 - 2 * C_DIM];
            } else {
                b0 = bias[col]; b1 = bias[col + 1];
            }
            float v0 = acc[ma][na][0] + b0;
            float v1 = acc[ma][na][1] + b1;
            float v2 = acc[ma][na][2] + b0;
            float v3 = acc[ma][na][3] + b1;
            if (EPI == 2) {
                v0 += R[(size_t)row0 * N + col];     v1 += R[(size_t)row0 * N + col + 1];
                v2 += R[(size_t)row1 * N + col];     v3 += R[(size_t)row1 * N + col + 1];
            }
            if (EPI == 3) {
                v0 = 0.5f * v0 * (1.0f + erff(v0 * 0.70710678118654752f));
                v1 = 0.5f * v1 * (1.0f + erff(v1 * 0.70710678118654752f));
                v2 = 0.5f * v2 * (1.0f + erff(v2 * 0.70710678118654752f));
                v3 = 0.5f * v3 * (1.0f + erff(v3 * 0.70710678118654752f));
                __nv_bfloat162 h0, l0, h1, l1;
                h0.x = __float2bfloat16(v0); h0.y = __float2bfloat16(v1);
                l0.x = __float2bfloat16(v0 - __bfloat162float(h0.x));
                l0.y = __float2bfloat16(v1 - __bfloat162float(h0.y));
                h1.x = __float2bfloat16(v2); h1.y = __float2bfloat16(v3);
                l1.x = __float2bfloat16(v2 - __bfloat162float(h1.x));
                l1.y = __float2bfloat16(v3 - __bfloat162float(h1.y));
                __nv_bfloat16* c0 = Ce + (size_t)row0 * 3 * N;
                __nv_bfloat16* c1 = Ce + (size_t)row1 * 3 * N;
                *reinterpret_cast<__nv_bfloat162*>(c0 + col)         = h0;
                *reinterpret_cast<__nv_bfloat162*>(c0 + N + col)     = l0;
                *reinterpret_cast<__nv_bfloat162*>(c0 + 2 * N + col) = h0;
                *reinterpret_cast<__nv_bfloat162*>(c1 + col)         = h1;
                *reinterpret_cast<__nv_bfloat162*>(c1 + N + col)     = l1;
                *reinterpret_cast<__nv_bfloat162*>(c1 + 2 * N + col) = h1;
            } else {
                *reinterpret_cast<float2*>(Cout + (size_t)row0 * N + col) = make_float2(v0, v1);
                *reinterpret_cast<float2*>(Cout + (size_t)row1 * N + col) = make_float2(v2, v3);
            }
        }
    }
}

// ---------------------------------------------------------------------------
// Fused masked-causal attention, 4-way key batching (round-10 version).
// ---------------------------------------------------------------------------
__global__ __launch_bounds__(256)
void attn_kernel(const float* __restrict__ QKV, __nv_bfloat16* __restrict__ Ye)
{
    const int bh = blockIdx.x;
    const int b  = bh >> 4;
    const int h  = bh & 15;
    const int qbase = blockIdx.y * 8;
    const int warp = threadIdx.x >> 5;
    const int lane = threadIdx.x & 31;
    const int tq = qbase + warp;

    __shared__ float Ks[68][66];
    __shared__ float Vs[68][66];

    const size_t rq = (size_t)(b * T_SEQ + tq) * NQKV + h * HEAD_D;
    const float q0 = QKV[rq + lane * 2];
    const float q1 = QKV[rq + lane * 2 + 1];

    float m = -INFINITY, l = 0.f, acc0 = 0.f, acc1 = 0.f;
    const int smax = qbase + 7;

    for (int s0 = 0; s0 <= smax; s0 += 64) {
        const int tile = min(64, smax + 1 - s0);
        __syncthreads();
        for (int idx = threadIdx.x; idx < 68 * 64; idx += 256) {
            const int r = idx >> 6, cc = idx & 63;
            float kv = 0.f, vv = 0.f;
            if (r < tile) {
                const size_t g = (size_t)(b * T_SEQ + s0 + r) * NQKV + h * HEAD_D + cc;
                kv = QKV[g + C_DIM];
                vv = QKV[g + 2 * C_DIM];
            }
            Ks[r][cc] = kv; Vs[r][cc] = vv;
        }
        __syncthreads();

        const int rend = min(tq, s0 + 63) - s0;
        for (int r = 0; r <= rend; r += 4) {
            float p[4];
#pragma unroll
            for (int j = 0; j < 4; ++j)
                p[j] = q0 * Ks[r + j][lane * 2] + q1 * Ks[r + j][lane * 2 + 1];
#pragma unroll
            for (int off = 16; off; off >>= 1) {
#pragma unroll
                for (int j = 0; j < 4; ++j)
                    p[j] += __shfl_xor_sync(~0u, p[j], off);
            }
#pragma unroll
            for (int j = 0; j < 4; ++j) {
                const int s = s0 + r + j;
                const bool valid = (s <= tq) && ((s & 15) != 15);
                p[j] = valid ? p[j] * 0.125f : -INFINITY;
            }
            const float mnew = fmaxf(fmaxf(fmaxf(p[0], p[1]), fmaxf(p[2], p[3])), m);
            const float corr = __expf(m - mnew);
            const float w0 = __expf(p[0] - mnew);
            const float w1 = __expf(p[1] - mnew);
            const float w2 = __expf(p[2] - mnew);
            const float w3 = __expf(p[3] - mnew);
            l = l * corr + ((w0 + w1) + (w2 + w3));
            acc0 = acc0 * corr + w0 * Vs[r][lane * 2]     + w1 * Vs[r + 1][lane * 2]
                               + w2 * Vs[r + 2][lane * 2] + w3 * Vs[r + 3][lane * 2];
            acc1 = acc1 * corr + w0 * Vs[r][lane * 2 + 1]     + w1 * Vs[r + 1][lane * 2 + 1]
                               + w2 * Vs[r + 2][lane * 2 + 1] + w3 * Vs[r + 3][lane * 2 + 1];
            m = mnew;
        }
    }
    const float inv = 1.0f / l;
    const float o0 = acc0 * inv, o1 = acc1 * inv;

    const int row = b * T_SEQ + tq;
    const int c = h * HEAD_D + lane * 2;
    __nv_bfloat162 hi2, lo2;
    hi2.x = __float2bfloat16(o0); hi2.y = __float2bfloat16(o1);
    lo2.x = __float2bfloat16(o0 - __bfloat162float(hi2.x));
    lo2.y = __float2bfloat16(o1 - __bfloat162float(hi2.y));
    __nv_bfloat16* yr = Ye + (size_t)row * K3C;
    *reinterpret_cast<__nv_bfloat162*>(yr + c)             = hi2;
    *reinterpret_cast<__nv_bfloat162*>(yr + C_DIM + c)     = lo2;
    *reinterpret_cast<__nv_bfloat162*>(yr + 2 * C_DIM + c) = hi2;
}

// ---------------------------------------------------------------------------
// EinLinear head
// ---------------------------------------------------------------------------
__global__ __launch_bounds__(256)
void head_kernel(const float* __restrict__ X, const float* __restrict__ Wh,
                 float* __restrict__ out)
{
    const int e     = blockIdx.x & 15;
    const int chunk = blockIdx.x >> 4;
    const int tid = threadIdx.x;
    const int warp = tid >> 5, lane = tid & 31;

    __shared__ float xs[8][C_DIM];
    int rows[8];
#pragma unroll
    for (int j = 0; j < 8; ++j) rows[j] = (chunk * 8 + j) * TRANS + e;

#pragma unroll
    for (int j = 0; j < 8; ++j)
        for (int idx = tid; idx < C_DIM; idx += 256)
            xs[j][idx] = X[(size_t)rows[j] * C_DIM + idx];
    __syncthreads();

    for (int o = warp; o < VOCABP1; o += 8) {
        const float* w = Wh + ((size_t)e * VOCABP1 + o) * C_DIM;
        float a[8];
#pragma unroll
        for (int j = 0; j < 8; ++j) a[j] = 0.f;
        for (int k = lane; k < C_DIM; k += 32) {
            const float wv = w[k];
#pragma unroll
            for (int j = 0; j < 8; ++j) a[j] += wv * xs[j][k];
        }
#pragma unroll
        for (int j = 0; j < 8; ++j)
#pragma unroll
            for (int off = 16; off; off >>= 1)
                a[j] += __shfl_xor_sync(~0u, a[j], off);
        if (lane == 0) {
#pragma unroll
            for (int j = 0; j < 8; ++j)
                out[(size_t)rows[j] * VOCABP1 + o] = a[j];
        }
    }
}

// ---------------------------------------------------------------------------
// Launch
// ---------------------------------------------------------------------------
extern "C" void kernel_launch(void* const* d_in, const int* in_sizes, int n_in,
                              void* d_out, int out_size)
{
    const int*   tokens  = (const int*)  d_in[0];
    const float* tok_emb = (const float*)d_in[1];
    const float* pos_emb = (const float*)d_in[2];
    const float* Wq = (const float*)d_in[3];  const float* bq = (const float*)d_in[4];
    const float* Wk = (const float*)d_in[5];  const float* bk = (const float*)d_in[6];
    const float* Wv = (const float*)d_in[7];  const float* bv = (const float*)d_in[8];
    const float* Wp = (const float*)d_in[9];  const float* bp = (const float*)d_in[10];
    const float* ln1w = (const float*)d_in[11]; const float* ln1b = (const float*)d_in[12];
    const float* ln2w = (const float*)d_in[13]; const float* ln2b = (const float*)d_in[14];
    const float* W1 = (const float*)d_in[15]; const float* b1 = (const float*)d_in[16];
    const float* W2 = (const float*)d_in[17]; const float* b2 = (const float*)d_in[18];
    const float* lnfw = (const float*)d_in[19]; const float* lnfb = (const float*)d_in[20];
    const float* head_w = (const float*)d_in[21];

    float *x, *h, *qkv, *part;
    __nv_bfloat16 *aC, *aF, *wqkvx, *wpx, *w1x, *w2x;
    cudaGetSymbolAddress((void**)&x,    g_x);
    cudaGetSymbolAddress((void**)&h,    g_h);
    cudaGetSymbolAddress((void**)&qkv,  g_qkv);
    cudaGetSymbolAddress((void**)&part, g_part);
    cudaGetSymbolAddress((void**)&aC,   g_aexpC);
    cudaGetSymbolAddress((void**)&aF,   g_aexpF);
    cudaGetSymbolAddress((void**)&wqkvx, g_wqkv);
    cudaGetSymbolAddress((void**)&wpx,  g_wp);
    cudaGetSymbolAddress((void**)&w1x,  g_w1);
    cudaGetSymbolAddress((void**)&w2x,  g_w2);

    cudaFuncSetAttribute(mma_gemm<0>, cudaFuncAttributeMaxDynamicSharedMemorySize, G_SMEM);
    cudaFuncSetAttribute(mma_gemm<2>, cudaFuncAttributeMaxDynamicSharedMemorySize, G_SMEM);
    cudaFuncSetAttribute(mma_gemm<3>, cudaFuncAttributeMaxDynamicSharedMemorySize, G_SMEM);
    cudaFuncSetAttribute(mma_gemm<4>, cudaFuncAttributeMaxDynamicSharedMemorySize, G_SMEM);

    const dim3 wb(32, 8);
    const dim3 gQKV(NQKV   / 128, ROWS / 128);        // (24, 16)
    const dim3 gF4 (F4_DIM / 128, ROWS / 128);        // (32, 16)
    const dim3 gCsp(C_DIM  / 128, ROWS / 128, 2);     // (8, 16, 2) split-K
    const dim3 gAtt(B_SZ * N_HEADS, T_SEQ / 8);
    const int  gRed = ROWS * C_DIM / 4 / 256;         // 2048 blocks

    // weight expansion (all layers, z-batched)
    expand_wT<<<dim3(32, 32, N_LAYER), wb>>>(Wq, wqkvx,
        C_DIM, C_DIM, (size_t)C_DIM * C_DIM, (size_t)NQKV * K3C);
    expand_wT<<<dim3(32, 32, N_LAYER), wb>>>(Wk, wqkvx + (size_t)C_DIM * K3C,
        C_DIM, C_DIM, (size_t)C_DIM * C_DIM, (size_t)NQKV * K3C);
    expand_wT<<<dim3(32, 32, N_LAYER), wb>>>(Wv, wqkvx + (size_t)2 * C_DIM * K3C,
        C_DIM, C_DIM, (size_t)C_DIM * C_DIM, (size_t)NQKV * K3C);
    expand_wT<<<dim3(32, 32, N_LAYER), wb>>>(Wp, wpx,
        C_DIM, C_DIM, (size_t)C_DIM * C_DIM, (size_t)C_DIM * K3C);
    expand_wT<<<dim3(32, 128, N_LAYER), wb>>>(W1, w1x,
        C_DIM, F4_DIM, (size_t)C_DIM * F4_DIM, (size_t)F4_DIM * K3C);
    expand_wT<<<dim3(128, 32, N_LAYER), wb>>>(W2, w2x,
        F4_DIM, C_DIM, (size_t)F4_DIM * C_DIM, (size_t)C_DIM * K3F);

    embed_kernel<<<ROWS * C_DIM / 256, 256>>>(tokens, tok_emb, pos_emb, x);

    for (int i = 0; i < N_LAYER; ++i) {
        const size_t bc = (size_t)i * C_DIM;

        ln_kernel<1><<<ROWS, 256>>>(x, ln1w + bc, ln1b + bc, nullptr, aC);
        mma_gemm<4><<<gQKV, 256, G_SMEM>>>(aC, wqkvx + (size_t)i * NQKV * K3C,
                                           bq + bc, bk + bc, bv + bc, nullptr,
                                           qkv, nullptr, NQKV, K3C, K3C);

        attn_kernel<<<gAtt, 256>>>(qkv, aC);

        // proj: split-K2 -> partials -> reduce into x
        mma_gemm<0><<<gCsp, 256, G_SMEM>>>(aC, wpx + (size_t)i * C_DIM * K3C,
                                           nullptr, nullptr, nullptr, nullptr,
                                           part, nullptr, C_DIM, K3C, K3C / 2);
        reduce2_kernel<<<gRed, 256>>>((const float4*)part, (const float4*)(bp + bc),
                                      (float4*)x);

        ln_kernel<1><<<ROWS, 256>>>(x, ln2w + bc, ln2b + bc, nullptr, aC);
        mma_gemm<3><<<gF4, 256, G_SMEM>>>(aC, w1x + (size_t)i * F4_DIM * K3C,
                                          b1 + (size_t)i * F4_DIM, nullptr, nullptr, nullptr,
                                          nullptr, aF, F4_DIM, K3C, K3C);

        // W2: split-K2 -> partials -> reduce into x
        mma_gemm<0><<<gCsp, 256, G_SMEM>>>(aF, w2x + (size_t)i * C_DIM * K3F,
                                           nullptr, nullptr, nullptr, nullptr,
                                           part, nullptr, C_DIM, K3F, K3F / 2);
        reduce2_kernel<<<gRed, 256>>>((const float4*)part, (const float4*)(b2 + bc),
                                      (float4*)x);
    }

    ln_kernel<0><<<ROWS, 256>>>(x, lnfw, lnfb, h, nullptr);
    head_kernel<<<256, 256>>>(h, head_w, (float*)d_out);
}